// round 13
// baseline (speedup 1.0000x reference)
#include <cuda_runtime.h>
#include <cuda_bf16.h>
#include <cstdint>

typedef unsigned long long ull;

#define EPSF 1e-5f

// ---------------- scratch ----------------
__device__ __nv_bfloat16 g_P2h[(size_t)13 * 256 * 256];  // [e][col][k] hi plane
__device__ __nv_bfloat16 g_P2l[(size_t)13 * 256 * 256];  // [e][col][k] lo plane
__device__ float g_Pb[208 * 16];                // [m][a16], 0.5 folded bias
__device__ float g_W1T[256 * 128];              // [c][f], BN-scale folded
__device__ float g_bf[128];                     // folded bias
__device__ float g_att[(size_t)13312 * 256];    // attention out, row = a*1024 + b

// ---------------- helpers ----------------
__device__ __forceinline__ ull fma2(ull a, ull b, ull c) {
    ull d;
    asm("fma.rn.f32x2 %0, %1, %2, %3;" : "=l"(d) : "l"(a), "l"(b), "l"(c));
    return d;
}
__device__ __forceinline__ ull dup2(float v) {
    ull d; unsigned r = __float_as_uint(v);
    asm("mov.b64 %0, {%1, %1};" : "=l"(d) : "r"(r));
    return d;
}
__device__ __forceinline__ float lo32(ull a) { return __uint_as_float((unsigned)(a & 0xffffffffull)); }
__device__ __forceinline__ float hi32(ull a) { return __uint_as_float((unsigned)(a >> 32)); }

__device__ __forceinline__ void cpa16(unsigned dst, const void* src) {
    asm volatile("cp.async.ca.shared.global [%0], [%1], 16;" :: "r"(dst), "l"(src));
}
__device__ __forceinline__ void cpa_commit() {
    asm volatile("cp.async.commit_group;" ::: "memory");
}
__device__ __forceinline__ void cpa_wait0() {
    asm volatile("cp.async.wait_group 0;" ::: "memory");
}
__device__ __forceinline__ unsigned s32(const void* p) {
    return (unsigned)__cvta_generic_to_shared(p);
}
__device__ __forceinline__ void ldmx4(unsigned* r, unsigned addr) {
    asm volatile("ldmatrix.sync.aligned.m8n8.x4.shared.b16 {%0,%1,%2,%3}, [%4];"
        : "=r"(r[0]), "=r"(r[1]), "=r"(r[2]), "=r"(r[3]) : "r"(addr));
}
__device__ __forceinline__ void mma16816(float* d, const unsigned* a, const unsigned* b) {
    asm volatile(
        "mma.sync.aligned.m16n8k16.row.col.f32.bf16.bf16.f32 "
        "{%0,%1,%2,%3}, {%4,%5,%6,%7}, {%8,%9}, {%0,%1,%2,%3};"
        : "+f"(d[0]), "+f"(d[1]), "+f"(d[2]), "+f"(d[3])
        : "r"(a[0]), "r"(a[1]), "r"(a[2]), "r"(a[3]), "r"(b[0]), "r"(b[1]));
}
__device__ __forceinline__ void barSync(int id, int cnt) {
    asm volatile("bar.sync %0, %1;" :: "r"(id), "r"(cnt) : "memory");
}
__device__ __forceinline__ void barArrive(int id, int cnt) {
    asm volatile("bar.arrive %0, %1;" :: "r"(id), "r"(cnt) : "memory");
}

// ================= dummy (ncu capture alignment: capture = 4th launch) =====
__global__ void k_nop() {}

// ================= fold Q into Wk, bf16-split, [e][col][k] layout ==========
__global__ void k_precompP2(const float* __restrict__ Q,
                            const float* __restrict__ Wk,
                            const float* __restrict__ bk) {
    int e = blockIdx.x >> 4;       // 0..12
    int S = blockIdx.x & 15;       // 0..15 (= hk)
    int k = threadIdx.x;           // 0..255
    int m = S * 13 + e;            // 0..207
    const float* qp = Q + m * 4;
    float q0 = qp[0], q1 = qp[1], q2 = qp[2], q3 = qp[3];
    __nv_bfloat16* dh = g_P2h + ((size_t)e * 256 + S * 16) * 256 + k;
    __nv_bfloat16* dl = g_P2l + ((size_t)e * 256 + S * 16) * 256 + k;
    #pragma unroll
    for (int a = 0; a < 13; ++a) {
        const float* wv = Wk + (size_t)(a * 64 + S * 4) * 256 + k;
        float s = 0.5f * (q0 * wv[0] + q1 * wv[256] + q2 * wv[512] + q3 * wv[768]);
        __nv_bfloat16 hi = __float2bfloat16(s);
        dh[(size_t)a * 256] = hi;
        dl[(size_t)a * 256] = __float2bfloat16(s - __bfloat162float(hi));
    }
    #pragma unroll
    for (int a = 13; a < 16; ++a) {
        dh[(size_t)a * 256] = __float2bfloat16(0.f);
        dl[(size_t)a * 256] = __float2bfloat16(0.f);
    }
    if (k < 16) {
        float v = 0.f;
        if (k < 13) {
            const float* bb = bk + k * 64 + S * 4;
            v = 0.5f * (q0 * bb[0] + q1 * bb[1] + q2 * bb[2] + q3 * bb[3]);
        }
        g_Pb[m * 16 + k] = v;
    }
}

// ================= fold BN into W1, transpose =================
__global__ void k_foldW1(const float* __restrict__ W1, const float* __restrict__ b1,
                         const float* __restrict__ bnw, const float* __restrict__ bnb,
                         const float* __restrict__ bnrm, const float* __restrict__ bnrv) {
    int f = blockIdx.x;    // 0..127
    int c = threadIdx.x;   // 0..255
    float s = bnw[f] * rsqrtf(bnrv[f] + EPSF);
    g_W1T[c * 128 + f] = W1[f * 256 + c] * s;
    if (c == 0) g_bf[f] = b1[f] * s + bnb[f] - bnrm[f] * s;
}

// ================= attention: warp-specialized pipeline =====================
// Warps 0-7: B staging + bf16-split MMA -> MS[parity].   Warps 8-15: epilogue.
// smem bytes:
//   AH @ 0      : 64 x 528 (A hi)          33,792
//   AL @ 33792  : 64 x 528 (A lo)          33,792
//   BS @ 67584  : 2 bufs x (2 planes x 128 col x 80)   40,960
//   MS @ 108544 : 2 bufs x (64 t x 132 col fp32)       67,584   (sx aliased on buf0)
//   PB @ 176128 : 16 warps x 64 fp32        4,096
#define AH_OFF  0
#define AL_OFF  33792
#define BS_OFF  67584
#define MS_OFF  108544
#define PBF_OFF 176128
#define SMEM_ATT_BYTES 180224
#define BS_BUF 20480
#define MS_BUF 8448   /* floats */

__global__ void __launch_bounds__(512, 1) k_attention(
    const float* __restrict__ x, const float* __restrict__ Wc,
    const float* __restrict__ bc, const float* __restrict__ ginw,
    const float* __restrict__ ginb) {
    extern __shared__ char smc[];
    __nv_bfloat16* AH = (__nv_bfloat16*)(smc + AH_OFF);
    __nv_bfloat16* AL = (__nv_bfloat16*)(smc + AL_OFF);
    float* MS  = (float*)(smc + MS_OFF);
    float* sx  = MS;                      // alias: x staging, pre-GEMM only
    float* pbuf = (float*)(smc + PBF_OFF);
    const int tid = threadIdx.x;
    const int b = blockIdx.x;

    // stage x[b] (600 floats)
    for (int i = tid; i < 150; i += 512)
        ((float4*)sx)[i] = ((const float4*)(x + (size_t)b * 600))[i];
    __syncthreads();

    // ---- conv1x1 + GroupNorm(16 groups): thread pair per channel ----
    {
        const int c = tid >> 1;
        const int th = tid & 1;
        float wr[10];
        #pragma unroll
        for (int i = 0; i < 10; ++i) wr[i] = Wc[c * 10 + i];
        const float bb = bc[c];
        float vv[30];
        float s1 = 0.f, s2 = 0.f;
        #pragma unroll 6
        for (int tt = 0; tt < 30; ++tt) {
            const float* xr = sx + (th * 30 + tt) * 10;
            float h = bb;
            #pragma unroll
            for (int i = 0; i < 10; ++i) h = fmaf(wr[i], xr[i], h);
            vv[tt] = h; s1 += h; s2 = fmaf(h, h, s2);
        }
        #pragma unroll
        for (int o = 16; o; o >>= 1) {
            s1 += __shfl_xor_sync(0xffffffffu, s1, o);
            s2 += __shfl_xor_sync(0xffffffffu, s2, o);
        }
        float mean = s1 * (1.f / 960.f);
        float var = s2 * (1.f / 960.f) - mean * mean;
        float sc = ginw[c] * rsqrtf(var + EPSF);
        float sh = ginb[c] - mean * sc;
        __syncthreads();   // all conv reads of sx done before MS buf0 is reused
        #pragma unroll 6
        for (int tt = 0; tt < 30; ++tt) {
            int t = th * 30 + tt;
            float v = fmaf(vv[tt], sc, sh);
            __nv_bfloat16 hi = __float2bfloat16(v);
            AH[t * 264 + c] = hi;
            AL[t * 264 + c] = __float2bfloat16(v - __bfloat162float(hi));
        }
    }
    // zero A pad rows t = 60..63 (both planes, incl. col pad)
    for (int i = tid; i < 4 * 264; i += 512) {
        int rr = 60 + i / 264, cc = i % 264;
        AH[rr * 264 + cc] = __float2bfloat16(0.f);
        AL[rr * 264 + cc] = __float2bfloat16(0.f);
    }
    __syncthreads();

    const int e0 = (b * 13) >> 10;
    const int e12 = (b * 13 + 12) >> 10;
    const int nchunks = (e0 == e12) ? 2 : 4;
    const int w = tid >> 5;
    const int lane = tid & 31;

    if (w < 8) {
        // ================= GEMM + staging group (256 threads) =================
        const int mt = w >> 2;          // m-tile 0..1 (rows mt*32..+32)
        const int nq = w & 3;           // n-quad 0..3 (cols nq*32..+32)
        const int g = lane >> 2;
        const int t4 = lane & 3;

        // staging: thread covers full 64B payload of (spl, sq)
        const int spl = tid >> 7;              // 0 = hi, 1 = lo
        const int sq = tid & 127;              // local col
        const unsigned bs_t = s32(smc + BS_OFF) + (unsigned)(spl * 10240 + sq * 80);
        const __nv_bfloat16* gsrc = spl ? g_P2l : g_P2h;

        const unsigned aA_lane = (unsigned)((lane & 15) * 528 + ((lane >> 4) & 1) * 16);
        const unsigned aAH0 = s32(AH) + (unsigned)(mt * 32 * 528) + aA_lane;
        const unsigned aAH1 = aAH0 + 16 * 528;
        const unsigned aAL0 = s32(AL) + (unsigned)(mt * 32 * 528) + aA_lane;
        const unsigned aAL1 = aAL0 + 16 * 528;
        const int bgrp = lane >> 3, blr = lane & 7;
        const unsigned bs_lane = (unsigned)((nq * 32 + (bgrp >> 1) * 8 + blr) * 80 + (bgrp & 1) * 16);
        const unsigned bsm = s32(smc + BS_OFF);

        for (int chunk = 0; chunk < nchunks; ++chunk) {
            const int p = chunk & 1;
            const int ec = e0 + (chunk >> 1);
            const size_t qb = ((size_t)ec * 256 + p * 128 + sq) * 256;

            float D[2][16];
            #pragma unroll
            for (int i = 0; i < 2; ++i)
                #pragma unroll
                for (int j = 0; j < 16; ++j) D[i][j] = 0.f;

            // prologue: prefetch round 0 (64 B per thread)
            {
                const __nv_bfloat16* s = gsrc + qb;
                cpa16(bs_t, s);
                cpa16(bs_t + 16, s + 8);
                cpa16(bs_t + 32, s + 16);
                cpa16(bs_t + 48, s + 24);
                cpa_commit();
            }

            for (int r = 0; r < 8; ++r) {
                cpa_wait0();
                barSync(1, 256);
                if (r + 1 < 8) {
                    unsigned d = bs_t + (unsigned)(((r + 1) & 1) * BS_BUF);
                    const __nv_bfloat16* s = gsrc + qb + (size_t)(r + 1) * 32;
                    cpa16(d, s);
                    cpa16(d + 16, s + 8);
                    cpa16(d + 32, s + 16);
                    cpa16(d + 48, s + 24);
                    cpa_commit();
                }
                const unsigned bufof = (unsigned)((r & 1) * BS_BUF);
                const unsigned kbyte = (unsigned)(r * 64);
                #pragma unroll
                for (int ks2 = 0; ks2 < 2; ++ks2) {
                    unsigned ah0[4], ah1[4], al0[4], al1[4];
                    ldmx4(ah0, aAH0 + kbyte + ks2 * 32);
                    ldmx4(ah1, aAH1 + kbyte + ks2 * 32);
                    ldmx4(al0, aAL0 + kbyte + ks2 * 32);
                    ldmx4(al1, aAL1 + kbyte + ks2 * 32);
                    unsigned bh0[4], bh1[4], bl0[4], bl1[4];
                    unsigned bb = bsm + bufof + bs_lane + (unsigned)(ks2 * 32);
                    ldmx4(bh0, bb);
                    ldmx4(bh1, bb + 16 * 80);
                    ldmx4(bl0, bb + 10240);
                    ldmx4(bl1, bb + 10240 + 16 * 80);
                    #pragma unroll
                    for (int nt = 0; nt < 4; ++nt) {
                        const unsigned* bh = (nt < 2 ? bh0 : bh1) + (nt & 1) * 2;
                        const unsigned* bl = (nt < 2 ? bl0 : bl1) + (nt & 1) * 2;
                        mma16816(D[0] + nt * 4, ah0, bh);
                        mma16816(D[0] + nt * 4, ah0, bl);
                        mma16816(D[0] + nt * 4, al0, bh);
                        mma16816(D[1] + nt * 4, ah1, bh);
                        mma16816(D[1] + nt * 4, ah1, bl);
                        mma16816(D[1] + nt * 4, al1, bh);
                    }
                }
            }

            // wait for MS[p] to be free (chunks >= 2 reuse the buffer)
            if (chunk >= 2) barSync(4 + p, 512);
            float* MSp = MS + p * MS_BUF;
            #pragma unroll
            for (int rh = 0; rh < 2; ++rh) {
                int row = mt * 32 + rh * 16 + g;
                #pragma unroll
                for (int nt = 0; nt < 4; ++nt) {
                    int col = nq * 32 + nt * 8 + t4 * 2;
                    *(float2*)&MSp[row * 132 + col] =
                        make_float2(D[rh][nt * 4 + 0], D[rh][nt * 4 + 1]);
                    *(float2*)&MSp[(row + 8) * 132 + col] =
                        make_float2(D[rh][nt * 4 + 2], D[rh][nt * 4 + 3]);
                }
            }
            barArrive(2 + p, 512);   // MS[p] full
        }
    } else {
        // ================= epilogue group (256 threads, warps 8..15) =========
        for (int chunk = 0; chunk < nchunks; ++chunk) {
            const int p = chunk & 1;
            const int ec = e0 + (chunk >> 1);
            barSync(2 + p, 512);     // wait MS[p] full
            const float* MSp = MS + p * MS_BUF;

            for (int r = w - 8; r < 104; r += 8) {
                int hkl = r / 13;
                int j = r - hkl * 13;
                int e = (b * 13 + j) >> 10;
                if (e != ec) continue;
                int hk = (p << 3) + hkl;
                int m = hk * 13 + e;
                int colb = hkl * 16;
                int val = j * 240 + lane * 4;
                int t = val / 52;
                int a = (val - t * 52) >> 2;
                float l1 = MSp[t * 132 + colb + a] + g_Pb[m * 16 + a];
                float l2 = -1e30f;
                if (lane < 28) {
                    int val2 = val + 128;
                    int t2 = val2 / 52;
                    int a2 = (val2 - t2 * 52) >> 2;
                    l2 = MSp[t2 * 132 + colb + a2] + g_Pb[m * 16 + a2];
                }
                float mx = fmaxf(l1, l2);
                #pragma unroll
                for (int o = 16; o; o >>= 1) mx = fmaxf(mx, __shfl_xor_sync(0xffffffffu, mx, o));
                float x1 = __expf(l1 - mx);
                float x2 = (lane < 28) ? __expf(l2 - mx) : 0.f;
                float sum = x1 + x2;
                #pragma unroll
                for (int o = 16; o; o >>= 1) sum += __shfl_xor_sync(0xffffffffu, sum, o);
                float inv = 1.f / sum;
                pbuf[w * 64 + lane] = x1 * inv;
                if (lane < 28) pbuf[w * 64 + 32 + lane] = x2 * inv;
                __syncwarp();
                // AV: v reconstructed from AH+AL (exact), lanes 0..15 t 0..29, 16..31 t 30..59
                int dh = lane & 15;
                int toff = (lane >> 4) * 30;
                int c = hk * 16 + dh;
                const float* pb = pbuf + w * 64 + toff;
                float a0 = 0.f, a1 = 0.f;
                #pragma unroll
                for (int tt = 0; tt < 15; ++tt) {
                    int t0i = toff + tt, t1i = toff + tt + 15;
                    float v0 = __bfloat162float(AH[t0i * 264 + c]) + __bfloat162float(AL[t0i * 264 + c]);
                    float v1 = __bfloat162float(AH[t1i * 264 + c]) + __bfloat162float(AL[t1i * 264 + c]);
                    a0 = fmaf(pb[tt], v0, a0);
                    a1 = fmaf(pb[tt + 15], v1, a1);
                }
                float acv = a0 + a1;
                acv += __shfl_xor_sync(0xffffffffu, acv, 16);
                if (lane < 16) {
                    int bq = (b * 13 + j) & 1023;
                    g_att[(size_t)((m >> 4) * 1024 + bq) * 256 + ((m & 15) << 4) + dh] = acv;
                }
                __syncwarp();
            }
            barArrive(4 + p, 512);   // MS[p] free
        }
    }
}

// ================= MLP + BN + ReLU + GroupNorm + permute =================
// 104 blocks x 128 rows (round-3 proven version, 37.4 us)
#define SO_OFF   0                          // [128][260]
#define SWC_OFF  (128*260)                  // [64][132]
#define SBF_OFF  (SWC_OFF + 64*132)
#define SGW_OFF  (SBF_OFF + 128)
#define SGB_OFF  (SGW_OFF + 128)
#define SMEM_MLP_FLOATS (SGB_OFF + 128)
#define SMEM_MLP_BYTES  (SMEM_MLP_FLOATS * 4)

__global__ void __launch_bounds__(256, 1) k_mlp(const float* __restrict__ gow,
                                                const float* __restrict__ gob,
                                                float* __restrict__ out) {
    extern __shared__ float sm[];
    float* sO  = sm + SO_OFF;
    float* sW  = sm + SWC_OFF;
    float* sBF = sm + SBF_OFF;
    float* sGW = sm + SGW_OFF;
    float* sGB = sm + SGB_OFF;
    const int tid = threadIdx.x;
    const int row0 = blockIdx.x * 128;

    for (int q = tid; q < 8192; q += 256) {
        int row = q >> 6, c4 = q & 63;
        *(float4*)(sO + row * 260 + c4 * 4) =
            *(const float4*)(g_att + (size_t)(row0 + row) * 256 + c4 * 4);
    }
    if (tid < 128) { sBF[tid] = g_bf[tid]; sGW[tid] = gow[tid]; sGB[tid] = gob[tid]; }

    const int rq = tid >> 3;       // 0..31
    const int fg = tid & 7;        // f = 16k + fg*2 + {0,1}
    ull acc[4][8];
    #pragma unroll
    for (int i = 0; i < 4; ++i)
        #pragma unroll
        for (int k = 0; k < 8; ++k) acc[i][k] = 0ull;

    for (int cc = 0; cc < 4; ++cc) {
        __syncthreads();
        for (int q = tid; q < 2048; q += 256) {
            int c = q >> 5, f4 = q & 31;
            *(float4*)(sW + c * 132 + f4 * 4) =
                *(const float4*)(g_W1T + (size_t)(cc * 64 + c) * 128 + f4 * 4);
        }
        __syncthreads();
        #pragma unroll 4
        for (int c = 0; c < 64; ++c) {
            const float* wr = sW + c * 132 + fg * 2;
            ull wv[8];
            #pragma unroll
            for (int k = 0; k < 8; ++k) wv[k] = *(const ull*)(wr + 16 * k);
            int cg = cc * 64 + c;
            #pragma unroll
            for (int i = 0; i < 4; ++i) {
                ull od = dup2(sO[(rq + 32 * i) * 260 + cg]);
                #pragma unroll
                for (int k = 0; k < 8; ++k)
                    acc[i][k] = fma2(od, wv[k], acc[i][k]);
            }
        }
    }

    #pragma unroll
    for (int i = 0; i < 4; ++i) {
        int r = row0 + rq + 32 * i;
        float* orow_out = out + (size_t)((r & 1023) * 13 + (r >> 10)) * 128;
        #pragma unroll
        for (int k = 0; k < 8; ++k) {
            int f = 16 * k + fg * 2;
            float y0 = fmaxf(lo32(acc[i][k]) + sBF[f], 0.f);
            float y1 = fmaxf(hi32(acc[i][k]) + sBF[f + 1], 0.f);
            float s = y0 + y1;
            float s2 = y0 * y0 + y1 * y1;
            s  += __shfl_xor_sync(0xffffffffu, s, 1);
            s2 += __shfl_xor_sync(0xffffffffu, s2, 1);
            s  += __shfl_xor_sync(0xffffffffu, s, 2);
            s2 += __shfl_xor_sync(0xffffffffu, s2, 2);
            float mean = s * 0.125f;
            float var = s2 * 0.125f - mean * mean;
            float sc = rsqrtf(var + EPSF);
            float o0 = (y0 - mean) * sc * sGW[f] + sGB[f];
            float o1 = (y1 - mean) * sc * sGW[f + 1] + sGB[f + 1];
            *(float2*)(orow_out + f) = make_float2(o0, o1);
        }
    }
}

// ================= launch =================
extern "C" void kernel_launch(void* const* d_in, const int* in_sizes, int n_in,
                              void* d_out, int out_size) {
    (void)in_sizes; (void)n_in; (void)out_size;
    const float* x    = (const float*)d_in[0];
    const float* Wc   = (const float*)d_in[1];
    const float* bc   = (const float*)d_in[2];
    const float* ginw = (const float*)d_in[3];
    const float* ginb = (const float*)d_in[4];
    const float* Q    = (const float*)d_in[5];
    const float* Wk   = (const float*)d_in[6];
    const float* bk   = (const float*)d_in[7];
    const float* W1   = (const float*)d_in[8];
    const float* b1   = (const float*)d_in[9];
    const float* bnw  = (const float*)d_in[10];
    const float* bnb  = (const float*)d_in[11];
    const float* bnrm = (const float*)d_in[12];
    const float* bnrv = (const float*)d_in[13];
    const float* gow  = (const float*)d_in[14];
    const float* gob  = (const float*)d_in[15];
    float* out = (float*)d_out;

    cudaFuncSetAttribute(k_attention, cudaFuncAttributeMaxDynamicSharedMemorySize, SMEM_ATT_BYTES);
    cudaFuncSetAttribute(k_mlp, cudaFuncAttributeMaxDynamicSharedMemorySize, SMEM_MLP_BYTES);

    k_precompP2<<<208, 256>>>(Q, Wk, bk);                      // launch 1
    k_foldW1<<<128, 256>>>(W1, b1, bnw, bnb, bnrm, bnrv);      // launch 2
    k_nop<<<1, 32>>>();                                        // launch 3
    k_attention<<<1024, 512, SMEM_ATT_BYTES>>>(x, Wc, bc, ginw, ginb);  // launch 4 (ncu target)
    k_mlp<<<104, 256, SMEM_MLP_BYTES>>>(gow, gob, out);        // launch 5
}

// round 14
// speedup vs baseline: 1.0138x; 1.0138x over previous
#include <cuda_runtime.h>
#include <cuda_bf16.h>
#include <cstdint>

typedef unsigned long long ull;

#define EPSF 1e-5f

// ---------------- scratch ----------------
__device__ __nv_bfloat16 g_P2h[(size_t)13 * 256 * 256];  // [e][col][k] hi plane
__device__ __nv_bfloat16 g_P2l[(size_t)13 * 256 * 256];  // [e][col][k] lo plane
__device__ float g_Pb[208 * 16];                // [m][a16], 0.5 folded bias
__device__ float g_W1T[256 * 128];              // [c][f], BN-scale folded
__device__ float g_bf[128];                     // folded bias
__device__ float g_att[(size_t)13312 * 256];    // attention out, row = a*1024 + b

// ---------------- helpers ----------------
__device__ __forceinline__ ull fma2(ull a, ull b, ull c) {
    ull d;
    asm("fma.rn.f32x2 %0, %1, %2, %3;" : "=l"(d) : "l"(a), "l"(b), "l"(c));
    return d;
}
__device__ __forceinline__ ull dup2(float v) {
    ull d; unsigned r = __float_as_uint(v);
    asm("mov.b64 %0, {%1, %1};" : "=l"(d) : "r"(r));
    return d;
}
__device__ __forceinline__ float lo32(ull a) { return __uint_as_float((unsigned)(a & 0xffffffffull)); }
__device__ __forceinline__ float hi32(ull a) { return __uint_as_float((unsigned)(a >> 32)); }

__device__ __forceinline__ void cpa16(unsigned dst, const void* src) {
    asm volatile("cp.async.ca.shared.global [%0], [%1], 16;" :: "r"(dst), "l"(src));
}
__device__ __forceinline__ void cpa_commit() {
    asm volatile("cp.async.commit_group;" ::: "memory");
}
__device__ __forceinline__ void cpa_wait0() {
    asm volatile("cp.async.wait_group 0;" ::: "memory");
}
__device__ __forceinline__ unsigned s32(const void* p) {
    return (unsigned)__cvta_generic_to_shared(p);
}
__device__ __forceinline__ void ldmx4(unsigned* r, unsigned addr) {
    asm volatile("ldmatrix.sync.aligned.m8n8.x4.shared.b16 {%0,%1,%2,%3}, [%4];"
        : "=r"(r[0]), "=r"(r[1]), "=r"(r[2]), "=r"(r[3]) : "r"(addr));
}
__device__ __forceinline__ void mma16816(float* d, const unsigned* a, const unsigned* b) {
    asm volatile(
        "mma.sync.aligned.m16n8k16.row.col.f32.bf16.bf16.f32 "
        "{%0,%1,%2,%3}, {%4,%5,%6,%7}, {%8,%9}, {%0,%1,%2,%3};"
        : "+f"(d[0]), "+f"(d[1]), "+f"(d[2]), "+f"(d[3])
        : "r"(a[0]), "r"(a[1]), "r"(a[2]), "r"(a[3]), "r"(b[0]), "r"(b[1]));
}

// ================= dummy (ncu capture alignment: capture = 4th launch) =====
__global__ void k_nop() {}

// ================= fold Q into Wk, bf16-split, [e][col][k] layout ==========
__global__ void k_precompP2(const float* __restrict__ Q,
                            const float* __restrict__ Wk,
                            const float* __restrict__ bk) {
    int e = blockIdx.x >> 4;       // 0..12
    int S = blockIdx.x & 15;       // 0..15 (= hk)
    int k = threadIdx.x;           // 0..255
    int m = S * 13 + e;            // 0..207
    const float* qp = Q + m * 4;
    float q0 = qp[0], q1 = qp[1], q2 = qp[2], q3 = qp[3];
    __nv_bfloat16* dh = g_P2h + ((size_t)e * 256 + S * 16) * 256 + k;
    __nv_bfloat16* dl = g_P2l + ((size_t)e * 256 + S * 16) * 256 + k;
    #pragma unroll
    for (int a = 0; a < 13; ++a) {
        const float* wv = Wk + (size_t)(a * 64 + S * 4) * 256 + k;
        float s = 0.5f * (q0 * wv[0] + q1 * wv[256] + q2 * wv[512] + q3 * wv[768]);
        __nv_bfloat16 hi = __float2bfloat16(s);
        dh[(size_t)a * 256] = hi;
        dl[(size_t)a * 256] = __float2bfloat16(s - __bfloat162float(hi));
    }
    #pragma unroll
    for (int a = 13; a < 16; ++a) {
        dh[(size_t)a * 256] = __float2bfloat16(0.f);
        dl[(size_t)a * 256] = __float2bfloat16(0.f);
    }
    if (k < 16) {
        float v = 0.f;
        if (k < 13) {
            const float* bb = bk + k * 64 + S * 4;
            v = 0.5f * (q0 * bb[0] + q1 * bb[1] + q2 * bb[2] + q3 * bb[3]);
        }
        g_Pb[m * 16 + k] = v;
    }
}

// ================= fold BN into W1, transpose =================
__global__ void k_foldW1(const float* __restrict__ W1, const float* __restrict__ b1,
                         const float* __restrict__ bnw, const float* __restrict__ bnb,
                         const float* __restrict__ bnrm, const float* __restrict__ bnrv) {
    int f = blockIdx.x;    // 0..127
    int c = threadIdx.x;   // 0..255
    float s = bnw[f] * rsqrtf(bnrv[f] + EPSF);
    g_W1T[c * 128 + f] = W1[f * 256 + c] * s;
    if (c == 0) g_bf[f] = b1[f] * s + bnb[f] - bnrm[f] * s;
}

// ================= attention: conv+GN, full-width bf16-split MMA, epilogue ==
// All 16 warps compute. One GEMM pass covers all 256 columns (16 hk).
// smem bytes:
//   AH @ 0      : 64 x 528 (A hi)                      33,792
//   AL @ 33792  : 64 x 528 (A lo)                      33,792
//   BS @ 67584  : 2 bufs x (2 planes x 256 col x 80)   81,920
//   MS @ 149504 : 64 t x 264 col fp32                  67,584  (sx aliased)
//   PB @ 217088 : 16 warps x 64 fp32                    4,096
#define AH_OFF  0
#define AL_OFF  33792
#define BS_OFF  67584
#define MS_OFF  149504
#define PBF_OFF 217088
#define SMEM_ATT_BYTES 221184
#define BS_BUF 40960

__global__ void __launch_bounds__(512, 1) k_attention(
    const float* __restrict__ x, const float* __restrict__ Wc,
    const float* __restrict__ bc, const float* __restrict__ ginw,
    const float* __restrict__ ginb) {
    extern __shared__ char smc[];
    __nv_bfloat16* AH = (__nv_bfloat16*)(smc + AH_OFF);
    __nv_bfloat16* AL = (__nv_bfloat16*)(smc + AL_OFF);
    float* MS  = (float*)(smc + MS_OFF);
    float* sx  = MS;                      // alias: x staging, pre-GEMM only
    float* pbuf = (float*)(smc + PBF_OFF);
    const int tid = threadIdx.x;
    const int b = blockIdx.x;

    // stage x[b] (600 floats)
    for (int i = tid; i < 150; i += 512)
        ((float4*)sx)[i] = ((const float4*)(x + (size_t)b * 600))[i];
    __syncthreads();

    // ---- conv1x1 + GroupNorm(16 groups): thread pair per channel ----
    {
        const int c = tid >> 1;
        const int th = tid & 1;
        float wr[10];
        #pragma unroll
        for (int i = 0; i < 10; ++i) wr[i] = Wc[c * 10 + i];
        const float bb = bc[c];
        float vv[30];
        float s1 = 0.f, s2 = 0.f;
        #pragma unroll 6
        for (int tt = 0; tt < 30; ++tt) {
            const float* xr = sx + (th * 30 + tt) * 10;
            float h = bb;
            #pragma unroll
            for (int i = 0; i < 10; ++i) h = fmaf(wr[i], xr[i], h);
            vv[tt] = h; s1 += h; s2 = fmaf(h, h, s2);
        }
        #pragma unroll
        for (int o = 16; o; o >>= 1) {
            s1 += __shfl_xor_sync(0xffffffffu, s1, o);
            s2 += __shfl_xor_sync(0xffffffffu, s2, o);
        }
        float mean = s1 * (1.f / 960.f);
        float var = s2 * (1.f / 960.f) - mean * mean;
        float sc = ginw[c] * rsqrtf(var + EPSF);
        float sh = ginb[c] - mean * sc;
        __syncthreads();   // all conv reads of sx done before MS is reused
        #pragma unroll 6
        for (int tt = 0; tt < 30; ++tt) {
            int t = th * 30 + tt;
            float v = fmaf(vv[tt], sc, sh);
            __nv_bfloat16 hi = __float2bfloat16(v);
            AH[t * 264 + c] = hi;
            AL[t * 264 + c] = __float2bfloat16(v - __bfloat162float(hi));
        }
    }
    // zero A pad rows t = 60..63 (both planes, incl. col pad)
    for (int i = tid; i < 4 * 264; i += 512) {
        int rr = 60 + i / 264, cc = i % 264;
        AH[rr * 264 + cc] = __float2bfloat16(0.f);
        AL[rr * 264 + cc] = __float2bfloat16(0.f);
    }
    __syncthreads();

    const int e0 = (b * 13) >> 10;
    const int e12 = (b * 13 + 12) >> 10;
    const int npass = (e0 == e12) ? 1 : 2;
    const int w = tid >> 5;
    const int lane = tid & 31;
    const int mt = w >> 3;          // m-tile 0..1 (rows mt*32..+32)
    const int nq = w & 7;           // n-octant 0..7 (cols nq*32..+32)
    const int g = lane >> 2;
    const int t4 = lane & 3;

    // staging: thread covers full 64B payload of (spl, sq) per round
    const int spl = tid >> 8;              // 0 = hi, 1 = lo
    const int sq = tid & 255;              // col 0..255
    const unsigned bs_t = s32(smc + BS_OFF) + (unsigned)(spl * 20480 + sq * 80);
    const __nv_bfloat16* gsrc = spl ? g_P2l : g_P2h;

    const unsigned aA_lane = (unsigned)((lane & 15) * 528 + ((lane >> 4) & 1) * 16);
    const unsigned aAH0 = s32(AH) + (unsigned)(mt * 32 * 528) + aA_lane;
    const unsigned aAH1 = aAH0 + 16 * 528;
    const unsigned aAL0 = s32(AL) + (unsigned)(mt * 32 * 528) + aA_lane;
    const unsigned aAL1 = aAL0 + 16 * 528;
    const int bgrp = lane >> 3, blr = lane & 7;
    const unsigned bs_lane = (unsigned)((nq * 32 + (bgrp >> 1) * 8 + blr) * 80 + (bgrp & 1) * 16);
    const unsigned bsm = s32(smc + BS_OFF);

    for (int pass = 0; pass < npass; ++pass) {
        const int ec = e0 + pass;
        const size_t qb = ((size_t)ec * 256 + sq) * 256;

        float D[2][16];
        #pragma unroll
        for (int i = 0; i < 2; ++i)
            #pragma unroll
            for (int j = 0; j < 16; ++j) D[i][j] = 0.f;

        // prologue: prefetch round 0 (64 B per thread)
        {
            const __nv_bfloat16* s = gsrc + qb;
            cpa16(bs_t, s);
            cpa16(bs_t + 16, s + 8);
            cpa16(bs_t + 32, s + 16);
            cpa16(bs_t + 48, s + 24);
            cpa_commit();
        }

        for (int r = 0; r < 8; ++r) {
            cpa_wait0();
            __syncthreads();
            if (r + 1 < 8) {
                unsigned d = bs_t + (unsigned)(((r + 1) & 1) * BS_BUF);
                const __nv_bfloat16* s = gsrc + qb + (size_t)(r + 1) * 32;
                cpa16(d, s);
                cpa16(d + 16, s + 8);
                cpa16(d + 32, s + 16);
                cpa16(d + 48, s + 24);
                cpa_commit();
            }
            const unsigned bufof = (unsigned)((r & 1) * BS_BUF);
            const unsigned kbyte = (unsigned)(r * 64);
            #pragma unroll
            for (int ks2 = 0; ks2 < 2; ++ks2) {
                unsigned ah0[4], ah1[4], al0[4], al1[4];
                ldmx4(ah0, aAH0 + kbyte + ks2 * 32);
                ldmx4(ah1, aAH1 + kbyte + ks2 * 32);
                ldmx4(al0, aAL0 + kbyte + ks2 * 32);
                ldmx4(al1, aAL1 + kbyte + ks2 * 32);
                unsigned bh0[4], bh1[4], bl0[4], bl1[4];
                unsigned bb = bsm + bufof + bs_lane + (unsigned)(ks2 * 32);
                ldmx4(bh0, bb);
                ldmx4(bh1, bb + 16 * 80);
                ldmx4(bl0, bb + 20480);
                ldmx4(bl1, bb + 20480 + 16 * 80);
                #pragma unroll
                for (int nt = 0; nt < 4; ++nt) {
                    const unsigned* bh = (nt < 2 ? bh0 : bh1) + (nt & 1) * 2;
                    const unsigned* bl = (nt < 2 ? bl0 : bl1) + (nt & 1) * 2;
                    mma16816(D[0] + nt * 4, ah0, bh);
                    mma16816(D[0] + nt * 4, ah0, bl);
                    mma16816(D[0] + nt * 4, al0, bh);
                    mma16816(D[1] + nt * 4, ah1, bh);
                    mma16816(D[1] + nt * 4, ah1, bl);
                    mma16816(D[1] + nt * 4, al1, bh);
                }
            }
        }

        // D -> MS (rows = t, cols 0..255, stride 264)
        #pragma unroll
        for (int rh = 0; rh < 2; ++rh) {
            int row = mt * 32 + rh * 16 + g;
            #pragma unroll
            for (int nt = 0; nt < 4; ++nt) {
                int col = nq * 32 + nt * 8 + t4 * 2;
                *(float2*)&MS[row * 264 + col] =
                    make_float2(D[rh][nt * 4 + 0], D[rh][nt * 4 + 1]);
                *(float2*)&MS[(row + 8) * 264 + col] =
                    make_float2(D[rh][nt * 4 + 2], D[rh][nt * 4 + 3]);
            }
        }
        __syncthreads();

        // ---- epilogue: all 208 rows (16 hk x 13 j) over 16 warps ----
        for (int r = w; r < 208; r += 16) {
            int hk = r / 13;
            int j = r - hk * 13;
            int e = (b * 13 + j) >> 10;
            if (e != ec) continue;
            int m = hk * 13 + e;
            int colb = hk * 16;
            int val = j * 240 + lane * 4;
            int t = val / 52;
            int a = (val - t * 52) >> 2;
            float l1 = MS[t * 264 + colb + a] + g_Pb[m * 16 + a];
            float l2 = -1e30f;
            if (lane < 28) {
                int val2 = val + 128;
                int t2 = val2 / 52;
                int a2 = (val2 - t2 * 52) >> 2;
                l2 = MS[t2 * 264 + colb + a2] + g_Pb[m * 16 + a2];
            }
            float mx = fmaxf(l1, l2);
            #pragma unroll
            for (int o = 16; o; o >>= 1) mx = fmaxf(mx, __shfl_xor_sync(0xffffffffu, mx, o));
            float x1 = __expf(l1 - mx);
            float x2 = (lane < 28) ? __expf(l2 - mx) : 0.f;
            float sum = x1 + x2;
            #pragma unroll
            for (int o = 16; o; o >>= 1) sum += __shfl_xor_sync(0xffffffffu, sum, o);
            float inv = 1.f / sum;
            pbuf[w * 64 + lane] = x1 * inv;
            if (lane < 28) pbuf[w * 64 + 32 + lane] = x2 * inv;
            __syncwarp();
            // AV: v = AH + AL (exact); lanes 0..15 sum t 0..29, lanes 16..31 t 30..59
            int dh = lane & 15;
            int toff = (lane >> 4) * 30;
            int c = hk * 16 + dh;
            const float* pb = pbuf + w * 64 + toff;
            float a0 = 0.f, a1 = 0.f;
            #pragma unroll
            for (int tt = 0; tt < 15; ++tt) {
                int t0i = toff + tt, t1i = toff + tt + 15;
                float v0 = __bfloat162float(AH[t0i * 264 + c]) + __bfloat162float(AL[t0i * 264 + c]);
                float v1 = __bfloat162float(AH[t1i * 264 + c]) + __bfloat162float(AL[t1i * 264 + c]);
                a0 = fmaf(pb[tt], v0, a0);
                a1 = fmaf(pb[tt + 15], v1, a1);
            }
            float acv = a0 + a1;
            acv += __shfl_xor_sync(0xffffffffu, acv, 16);
            if (lane < 16) {
                int bq = (b * 13 + j) & 1023;
                g_att[(size_t)((m >> 4) * 1024 + bq) * 256 + ((m & 15) << 4) + dh] = acv;
            }
            __syncwarp();
        }
        __syncthreads();   // MS reads done before next pass overwrites
    }
}

// ================= MLP + BN + ReLU + GroupNorm + permute =================
// 104 blocks x 128 rows (round-3 proven version, 37.4 us)
#define SO_OFF   0                          // [128][260]
#define SWC_OFF  (128*260)                  // [64][132]
#define SBF_OFF  (SWC_OFF + 64*132)
#define SGW_OFF  (SBF_OFF + 128)
#define SGB_OFF  (SGW_OFF + 128)
#define SMEM_MLP_FLOATS (SGB_OFF + 128)
#define SMEM_MLP_BYTES  (SMEM_MLP_FLOATS * 4)

__global__ void __launch_bounds__(256, 1) k_mlp(const float* __restrict__ gow,
                                                const float* __restrict__ gob,
                                                float* __restrict__ out) {
    extern __shared__ float sm[];
    float* sO  = sm + SO_OFF;
    float* sW  = sm + SWC_OFF;
    float* sBF = sm + SBF_OFF;
    float* sGW = sm + SGW_OFF;
    float* sGB = sm + SGB_OFF;
    const int tid = threadIdx.x;
    const int row0 = blockIdx.x * 128;

    for (int q = tid; q < 8192; q += 256) {
        int row = q >> 6, c4 = q & 63;
        *(float4*)(sO + row * 260 + c4 * 4) =
            *(const float4*)(g_att + (size_t)(row0 + row) * 256 + c4 * 4);
    }
    if (tid < 128) { sBF[tid] = g_bf[tid]; sGW[tid] = gow[tid]; sGB[tid] = gob[tid]; }

    const int rq = tid >> 3;       // 0..31
    const int fg = tid & 7;        // f = 16k + fg*2 + {0,1}
    ull acc[4][8];
    #pragma unroll
    for (int i = 0; i < 4; ++i)
        #pragma unroll
        for (int k = 0; k < 8; ++k) acc[i][k] = 0ull;

    for (int cc = 0; cc < 4; ++cc) {
        __syncthreads();
        for (int q = tid; q < 2048; q += 256) {
            int c = q >> 5, f4 = q & 31;
            *(float4*)(sW + c * 132 + f4 * 4) =
                *(const float4*)(g_W1T + (size_t)(cc * 64 + c) * 128 + f4 * 4);
        }
        __syncthreads();
        #pragma unroll 4
        for (int c = 0; c < 64; ++c) {
            const float* wr = sW + c * 132 + fg * 2;
            ull wv[8];
            #pragma unroll
            for (int k = 0; k < 8; ++k) wv[k] = *(const ull*)(wr + 16 * k);
            int cg = cc * 64 + c;
            #pragma unroll
            for (int i = 0; i < 4; ++i) {
                ull od = dup2(sO[(rq + 32 * i) * 260 + cg]);
                #pragma unroll
                for (int k = 0; k < 8; ++k)
                    acc[i][k] = fma2(od, wv[k], acc[i][k]);
            }
        }
    }

    #pragma unroll
    for (int i = 0; i < 4; ++i) {
        int r = row0 + rq + 32 * i;
        float* orow_out = out + (size_t)((r & 1023) * 13 + (r >> 10)) * 128;
        #pragma unroll
        for (int k = 0; k < 8; ++k) {
            int f = 16 * k + fg * 2;
            float y0 = fmaxf(lo32(acc[i][k]) + sBF[f], 0.f);
            float y1 = fmaxf(hi32(acc[i][k]) + sBF[f + 1], 0.f);
            float s = y0 + y1;
            float s2 = y0 * y0 + y1 * y1;
            s  += __shfl_xor_sync(0xffffffffu, s, 1);
            s2 += __shfl_xor_sync(0xffffffffu, s2, 1);
            s  += __shfl_xor_sync(0xffffffffu, s, 2);
            s2 += __shfl_xor_sync(0xffffffffu, s2, 2);
            float mean = s * 0.125f;
            float var = s2 * 0.125f - mean * mean;
            float sc = rsqrtf(var + EPSF);
            float o0 = (y0 - mean) * sc * sGW[f] + sGB[f];
            float o1 = (y1 - mean) * sc * sGW[f + 1] + sGB[f + 1];
            *(float2*)(orow_out + f) = make_float2(o0, o1);
        }
    }
}

// ================= launch =================
extern "C" void kernel_launch(void* const* d_in, const int* in_sizes, int n_in,
                              void* d_out, int out_size) {
    (void)in_sizes; (void)n_in; (void)out_size;
    const float* x    = (const float*)d_in[0];
    const float* Wc   = (const float*)d_in[1];
    const float* bc   = (const float*)d_in[2];
    const float* ginw = (const float*)d_in[3];
    const float* ginb = (const float*)d_in[4];
    const float* Q    = (const float*)d_in[5];
    const float* Wk   = (const float*)d_in[6];
    const float* bk   = (const float*)d_in[7];
    const float* W1   = (const float*)d_in[8];
    const float* b1   = (const float*)d_in[9];
    const float* bnw  = (const float*)d_in[10];
    const float* bnb  = (const float*)d_in[11];
    const float* bnrm = (const float*)d_in[12];
    const float* bnrv = (const float*)d_in[13];
    const float* gow  = (const float*)d_in[14];
    const float* gob  = (const float*)d_in[15];
    float* out = (float*)d_out;

    cudaFuncSetAttribute(k_attention, cudaFuncAttributeMaxDynamicSharedMemorySize, SMEM_ATT_BYTES);
    cudaFuncSetAttribute(k_mlp, cudaFuncAttributeMaxDynamicSharedMemorySize, SMEM_MLP_BYTES);

    k_precompP2<<<208, 256>>>(Q, Wk, bk);                      // launch 1
    k_foldW1<<<128, 256>>>(W1, b1, bnw, bnb, bnrm, bnrv);      // launch 2
    k_nop<<<1, 32>>>();                                        // launch 3
    k_attention<<<1024, 512, SMEM_ATT_BYTES>>>(x, Wc, bc, ginw, ginb);  // launch 4 (ncu target)
    k_mlp<<<104, 256, SMEM_MLP_BYTES>>>(gow, gob, out);        // launch 5
}

// round 15
// speedup vs baseline: 1.1450x; 1.1294x over previous
#include <cuda_runtime.h>
#include <cuda_bf16.h>
#include <cstdint>

typedef unsigned long long ull;

#define EPSF 1e-5f

// ---------------- scratch ----------------
__device__ __nv_bfloat16 g_P2h[(size_t)13 * 256 * 256];  // [e][col][k] hi plane
__device__ __nv_bfloat16 g_P2l[(size_t)13 * 256 * 256];  // [e][col][k] lo plane
__device__ float g_Pb[208 * 16];                // [m][a16], 0.5 folded bias
__device__ float g_W1T[256 * 128];              // [c][f], BN-scale folded
__device__ float g_bf[128];                     // folded bias
__device__ float g_att[(size_t)13312 * 256];    // attention out, row = a*1024 + b

// ---------------- helpers ----------------
__device__ __forceinline__ ull fma2(ull a, ull b, ull c) {
    ull d;
    asm("fma.rn.f32x2 %0, %1, %2, %3;" : "=l"(d) : "l"(a), "l"(b), "l"(c));
    return d;
}
__device__ __forceinline__ ull dup2(float v) {
    ull d; unsigned r = __float_as_uint(v);
    asm("mov.b64 %0, {%1, %1};" : "=l"(d) : "r"(r));
    return d;
}
__device__ __forceinline__ float lo32(ull a) { return __uint_as_float((unsigned)(a & 0xffffffffull)); }
__device__ __forceinline__ float hi32(ull a) { return __uint_as_float((unsigned)(a >> 32)); }

__device__ __forceinline__ void cpa16(unsigned dst, const void* src) {
    asm volatile("cp.async.ca.shared.global [%0], [%1], 16;" :: "r"(dst), "l"(src));
}
__device__ __forceinline__ void cpa_commit() {
    asm volatile("cp.async.commit_group;" ::: "memory");
}
__device__ __forceinline__ void cpa_wait0() {
    asm volatile("cp.async.wait_group 0;" ::: "memory");
}
__device__ __forceinline__ unsigned s32(const void* p) {
    return (unsigned)__cvta_generic_to_shared(p);
}
__device__ __forceinline__ void ldmx4(unsigned* r, unsigned addr) {
    asm volatile("ldmatrix.sync.aligned.m8n8.x4.shared.b16 {%0,%1,%2,%3}, [%4];"
        : "=r"(r[0]), "=r"(r[1]), "=r"(r[2]), "=r"(r[3]) : "r"(addr));
}
__device__ __forceinline__ void mma16816(float* d, const unsigned* a, const unsigned* b) {
    asm volatile(
        "mma.sync.aligned.m16n8k16.row.col.f32.bf16.bf16.f32 "
        "{%0,%1,%2,%3}, {%4,%5,%6,%7}, {%8,%9}, {%0,%1,%2,%3};"
        : "+f"(d[0]), "+f"(d[1]), "+f"(d[2]), "+f"(d[3])
        : "r"(a[0]), "r"(a[1]), "r"(a[2]), "r"(a[3]), "r"(b[0]), "r"(b[1]));
}

// ================= dummy (ncu capture alignment: capture = 4th launch) =====
__global__ void k_nop() {}

// ================= fold Q into Wk, bf16-split, [e][col][k] layout ==========
__global__ void k_precompP2(const float* __restrict__ Q,
                            const float* __restrict__ Wk,
                            const float* __restrict__ bk) {
    int e = blockIdx.x >> 4;       // 0..12
    int S = blockIdx.x & 15;       // 0..15 (= hk)
    int k = threadIdx.x;           // 0..255
    int m = S * 13 + e;            // 0..207
    const float* qp = Q + m * 4;
    float q0 = qp[0], q1 = qp[1], q2 = qp[2], q3 = qp[3];
    __nv_bfloat16* dh = g_P2h + ((size_t)e * 256 + S * 16) * 256 + k;
    __nv_bfloat16* dl = g_P2l + ((size_t)e * 256 + S * 16) * 256 + k;
    #pragma unroll
    for (int a = 0; a < 13; ++a) {
        const float* wv = Wk + (size_t)(a * 64 + S * 4) * 256 + k;
        float s = 0.5f * (q0 * wv[0] + q1 * wv[256] + q2 * wv[512] + q3 * wv[768]);
        __nv_bfloat16 hi = __float2bfloat16(s);
        dh[(size_t)a * 256] = hi;
        dl[(size_t)a * 256] = __float2bfloat16(s - __bfloat162float(hi));
    }
    #pragma unroll
    for (int a = 13; a < 16; ++a) {
        dh[(size_t)a * 256] = __float2bfloat16(0.f);
        dl[(size_t)a * 256] = __float2bfloat16(0.f);
    }
    if (k < 16) {
        float v = 0.f;
        if (k < 13) {
            const float* bb = bk + k * 64 + S * 4;
            v = 0.5f * (q0 * bb[0] + q1 * bb[1] + q2 * bb[2] + q3 * bb[3]);
        }
        g_Pb[m * 16 + k] = v;
    }
}

// ================= fold BN into W1, transpose =================
__global__ void k_foldW1(const float* __restrict__ W1, const float* __restrict__ b1,
                         const float* __restrict__ bnw, const float* __restrict__ bnb,
                         const float* __restrict__ bnrm, const float* __restrict__ bnrv) {
    int f = blockIdx.x;    // 0..127
    int c = threadIdx.x;   // 0..255
    float s = bnw[f] * rsqrtf(bnrv[f] + EPSF);
    g_W1T[c * 128 + f] = W1[f * 256 + c] * s;
    if (c == 0) g_bf[f] = b1[f] * s + bnb[f] - bnrm[f] * s;
}

// ================= attention: conv+GN, bf16-split MMA logits, softmax, AV ==
// Round-12 structure (two 128-col chunks, VT kept) but ALL 16 warps compute.
// smem bytes:
//   AH @ 0      : 64 x 528 (A hi)          33,792
//   AL @ 33792  : 64 x 528 (A lo)          33,792
//   BS @ 67584  : 2 bufs x (2 planes x 128 col x 80)   40,960
//   VT @ 108544 : 256 c x 68 t fp32        69,632
//   MS @ 178176 : 64 t x 132 col fp32      33,792  (sx aliased)
//   PB @ 211968 : 16 warps x 64 fp32        4,096
#define AH_OFF  0
#define AL_OFF  33792
#define BS_OFF  67584
#define VT_OFF  108544
#define MS_OFF  178176
#define PBF_OFF 211968
#define SMEM_ATT_BYTES 216064
#define BS_BUF 20480

__global__ void __launch_bounds__(512, 1) k_attention(
    const float* __restrict__ x, const float* __restrict__ Wc,
    const float* __restrict__ bc, const float* __restrict__ ginw,
    const float* __restrict__ ginb) {
    extern __shared__ char smc[];
    __nv_bfloat16* AH = (__nv_bfloat16*)(smc + AH_OFF);
    __nv_bfloat16* AL = (__nv_bfloat16*)(smc + AL_OFF);
    float* VT  = (float*)(smc + VT_OFF);
    float* MS  = (float*)(smc + MS_OFF);
    float* sx  = MS;                      // alias: x staging, pre-GEMM only
    float* pbuf = (float*)(smc + PBF_OFF);
    const int tid = threadIdx.x;
    const int b = blockIdx.x;

    // stage x[b] (600 floats)
    for (int i = tid; i < 150; i += 512)
        ((float4*)sx)[i] = ((const float4*)(x + (size_t)b * 600))[i];
    __syncthreads();

    // ---- conv1x1 + GroupNorm(16 groups): thread pair per channel ----
    {
        const int c = tid >> 1;
        const int th = tid & 1;
        float wr[10];
        #pragma unroll
        for (int i = 0; i < 10; ++i) wr[i] = Wc[c * 10 + i];
        const float bb = bc[c];
        float vv[30];
        float s1 = 0.f, s2 = 0.f;
        #pragma unroll 6
        for (int tt = 0; tt < 30; ++tt) {
            const float* xr = sx + (th * 30 + tt) * 10;
            float h = bb;
            #pragma unroll
            for (int i = 0; i < 10; ++i) h = fmaf(wr[i], xr[i], h);
            vv[tt] = h; s1 += h; s2 = fmaf(h, h, s2);
        }
        #pragma unroll
        for (int o = 16; o; o >>= 1) {
            s1 += __shfl_xor_sync(0xffffffffu, s1, o);
            s2 += __shfl_xor_sync(0xffffffffu, s2, o);
        }
        float mean = s1 * (1.f / 960.f);
        float var = s2 * (1.f / 960.f) - mean * mean;
        float sc = ginw[c] * rsqrtf(var + EPSF);
        float sh = ginb[c] - mean * sc;
        __syncthreads();   // all conv reads of sx done before MS is reused
        #pragma unroll 6
        for (int tt = 0; tt < 30; ++tt) {
            int t = th * 30 + tt;
            float v = fmaf(vv[tt], sc, sh);
            VT[c * 68 + t] = v;
            __nv_bfloat16 hi = __float2bfloat16(v);
            AH[t * 264 + c] = hi;
            AL[t * 264 + c] = __float2bfloat16(v - __bfloat162float(hi));
        }
        if (th == 1) {
            VT[c * 68 + 60] = 0.f; VT[c * 68 + 61] = 0.f;
            VT[c * 68 + 62] = 0.f; VT[c * 68 + 63] = 0.f;
        }
    }
    // zero A pad rows t = 60..63 (both planes, incl. col pad)
    for (int i = tid; i < 4 * 264; i += 512) {
        int rr = 60 + i / 264, cc = i % 264;
        AH[rr * 264 + cc] = __float2bfloat16(0.f);
        AL[rr * 264 + cc] = __float2bfloat16(0.f);
    }
    __syncthreads();

    const int e0 = (b * 13) >> 10;
    const int e12 = (b * 13 + 12) >> 10;
    const int nchunks = (e0 == e12) ? 2 : 4;
    const int w = tid >> 5;
    const int lane = tid & 31;
    const int mt = w >> 3;          // m-tile 0..1 (rows mt*32..+32)
    const int no8 = w & 7;          // 16-col group (cols no8*16..+16)
    const int g = lane >> 2;
    const int t4 = lane & 3;

    // staging: 512 threads x 32 B per round (2 planes x 128 cols x 64 B)
    const int spl = tid >> 8;              // 0 = hi, 1 = lo
    const int sq = (tid & 255) >> 1;       // local col 0..127
    const int sh_ = tid & 1;               // 32B half of the 64B round payload
    const unsigned bs_t = s32(smc + BS_OFF) + (unsigned)(spl * 10240 + sq * 80 + sh_ * 32);
    const __nv_bfloat16* gsrc = spl ? g_P2l : g_P2h;

    const unsigned aA_lane = (unsigned)((lane & 15) * 528 + ((lane >> 4) & 1) * 16);
    const unsigned aAH0 = s32(AH) + (unsigned)(mt * 32 * 528) + aA_lane;
    const unsigned aAH1 = aAH0 + 16 * 528;
    const unsigned aAL0 = s32(AL) + (unsigned)(mt * 32 * 528) + aA_lane;
    const unsigned aAL1 = aAL0 + 16 * 528;
    const int bgrp = lane >> 3, blr = lane & 7;
    const unsigned bs_lane = (unsigned)((no8 * 16 + (bgrp >> 1) * 8 + blr) * 80 + (bgrp & 1) * 16);
    const unsigned bsm = s32(smc + BS_OFF);

    for (int chunk = 0; chunk < nchunks; ++chunk) {
        const int p = chunk & 1;
        const int ec = e0 + (chunk >> 1);
        const size_t qb = ((size_t)ec * 256 + p * 128 + sq) * 256 + (size_t)sh_ * 16;

        float D[2][8];
        #pragma unroll
        for (int i = 0; i < 2; ++i)
            #pragma unroll
            for (int j = 0; j < 8; ++j) D[i][j] = 0.f;

        // prologue: prefetch round 0 (32 B per thread)
        {
            const __nv_bfloat16* s = gsrc + qb;
            cpa16(bs_t, s);
            cpa16(bs_t + 16, s + 8);
            cpa_commit();
        }

        for (int r = 0; r < 8; ++r) {
            cpa_wait0();
            __syncthreads();
            if (r + 1 < 8) {
                unsigned d = bs_t + (unsigned)(((r + 1) & 1) * BS_BUF);
                const __nv_bfloat16* s = gsrc + qb + (size_t)(r + 1) * 32;
                cpa16(d, s);
                cpa16(d + 16, s + 8);
                cpa_commit();
            }
            const unsigned bufof = (unsigned)((r & 1) * BS_BUF);
            const unsigned kbyte = (unsigned)(r * 64);
            #pragma unroll
            for (int ks2 = 0; ks2 < 2; ++ks2) {
                unsigned ah0[4], ah1[4], al0[4], al1[4];
                ldmx4(ah0, aAH0 + kbyte + ks2 * 32);
                ldmx4(ah1, aAH1 + kbyte + ks2 * 32);
                ldmx4(al0, aAL0 + kbyte + ks2 * 32);
                ldmx4(al1, aAL1 + kbyte + ks2 * 32);
                unsigned bh[4], bl[4];
                unsigned bb = bsm + bufof + bs_lane + (unsigned)(ks2 * 32);
                ldmx4(bh, bb);
                ldmx4(bl, bb + 10240);
                #pragma unroll
                for (int nt = 0; nt < 2; ++nt) {
                    const unsigned* bhf = bh + nt * 2;
                    const unsigned* blf = bl + nt * 2;
                    mma16816(D[0] + nt * 4, ah0, bhf);
                    mma16816(D[0] + nt * 4, ah0, blf);
                    mma16816(D[0] + nt * 4, al0, bhf);
                    mma16816(D[1] + nt * 4, ah1, bhf);
                    mma16816(D[1] + nt * 4, ah1, blf);
                    mma16816(D[1] + nt * 4, al1, bhf);
                }
            }
        }

        // D -> MS (rows = t, cols = chunk-local 0..127, stride 132)
        #pragma unroll
        for (int rh = 0; rh < 2; ++rh) {
            int row = mt * 32 + rh * 16 + g;
            #pragma unroll
            for (int nt = 0; nt < 2; ++nt) {
                int col = no8 * 16 + nt * 8 + t4 * 2;
                *(float2*)&MS[row * 132 + col] =
                    make_float2(D[rh][nt * 4 + 0], D[rh][nt * 4 + 1]);
                *(float2*)&MS[(row + 8) * 132 + col] =
                    make_float2(D[rh][nt * 4 + 2], D[rh][nt * 4 + 3]);
            }
        }
        __syncthreads();

        // ---- epilogue for this chunk: 104 rows (8 hk x 13 j) over 16 warps ----
        for (int r = w; r < 104; r += 16) {
            int hkl = r / 13;
            int j = r - hkl * 13;
            int e = (b * 13 + j) >> 10;
            if (e != ec) continue;
            int hk = (p << 3) + hkl;
            int m = hk * 13 + e;
            int colb = hkl * 16;
            int val = j * 240 + lane * 4;
            int t = val / 52;
            int a = (val - t * 52) >> 2;
            float l1 = MS[t * 132 + colb + a] + g_Pb[m * 16 + a];
            float l2 = -1e30f;
            if (lane < 28) {
                int val2 = val + 128;
                int t2 = val2 / 52;
                int a2 = (val2 - t2 * 52) >> 2;
                l2 = MS[t2 * 132 + colb + a2] + g_Pb[m * 16 + a2];
            }
            float mx = fmaxf(l1, l2);
            #pragma unroll
            for (int o = 16; o; o >>= 1) mx = fmaxf(mx, __shfl_xor_sync(0xffffffffu, mx, o));
            float x1 = __expf(l1 - mx);
            float x2 = (lane < 28) ? __expf(l2 - mx) : 0.f;
            float sum = x1 + x2;
            #pragma unroll
            for (int o = 16; o; o >>= 1) sum += __shfl_xor_sync(0xffffffffu, sum, o);
            float inv = 1.f / sum;
            pbuf[w * 64 + lane] = x1 * inv;
            if (lane < 28) pbuf[w * 64 + 32 + lane] = x2 * inv;
            __syncwarp();
            // AV: lanes 0..15 sum t 0..29, lanes 16..31 sum t 30..59
            int dh = lane & 15;
            int toff = (lane >> 4) * 30;
            const float* vcol = VT + (hk * 16 + dh) * 68 + toff;
            const float* pb = pbuf + w * 64 + toff;
            float a0 = 0.f, a1 = 0.f;
            #pragma unroll
            for (int tt = 0; tt < 15; ++tt) {
                a0 = fmaf(pb[tt], vcol[tt], a0);
                a1 = fmaf(pb[tt + 15], vcol[tt + 15], a1);
            }
            float acv = a0 + a1;
            acv += __shfl_xor_sync(0xffffffffu, acv, 16);
            if (lane < 16) {
                int bq = (b * 13 + j) & 1023;
                g_att[(size_t)((m >> 4) * 1024 + bq) * 256 + ((m & 15) << 4) + dh] = acv;
            }
            __syncwarp();
        }
        __syncthreads();   // MS reads done before next chunk overwrites
    }
}

// ================= MLP + BN + ReLU + GroupNorm + permute =================
// 104 blocks x 128 rows (round-3 proven version, 37.4 us)
#define SO_OFF   0                          // [128][260]
#define SWC_OFF  (128*260)                  // [64][132]
#define SBF_OFF  (SWC_OFF + 64*132)
#define SGW_OFF  (SBF_OFF + 128)
#define SGB_OFF  (SGW_OFF + 128)
#define SMEM_MLP_FLOATS (SGB_OFF + 128)
#define SMEM_MLP_BYTES  (SMEM_MLP_FLOATS * 4)

__global__ void __launch_bounds__(256, 1) k_mlp(const float* __restrict__ gow,
                                                const float* __restrict__ gob,
                                                float* __restrict__ out) {
    extern __shared__ float sm[];
    float* sO  = sm + SO_OFF;
    float* sW  = sm + SWC_OFF;
    float* sBF = sm + SBF_OFF;
    float* sGW = sm + SGW_OFF;
    float* sGB = sm + SGB_OFF;
    const int tid = threadIdx.x;
    const int row0 = blockIdx.x * 128;

    for (int q = tid; q < 8192; q += 256) {
        int row = q >> 6, c4 = q & 63;
        *(float4*)(sO + row * 260 + c4 * 4) =
            *(const float4*)(g_att + (size_t)(row0 + row) * 256 + c4 * 4);
    }
    if (tid < 128) { sBF[tid] = g_bf[tid]; sGW[tid] = gow[tid]; sGB[tid] = gob[tid]; }

    const int rq = tid >> 3;       // 0..31
    const int fg = tid & 7;        // f = 16k + fg*2 + {0,1}
    ull acc[4][8];
    #pragma unroll
    for (int i = 0; i < 4; ++i)
        #pragma unroll
        for (int k = 0; k < 8; ++k) acc[i][k] = 0ull;

    for (int cc = 0; cc < 4; ++cc) {
        __syncthreads();
        for (int q = tid; q < 2048; q += 256) {
            int c = q >> 5, f4 = q & 31;
            *(float4*)(sW + c * 132 + f4 * 4) =
                *(const float4*)(g_W1T + (size_t)(cc * 64 + c) * 128 + f4 * 4);
        }
        __syncthreads();
        #pragma unroll 4
        for (int c = 0; c < 64; ++c) {
            const float* wr = sW + c * 132 + fg * 2;
            ull wv[8];
            #pragma unroll
            for (int k = 0; k < 8; ++k) wv[k] = *(const ull*)(wr + 16 * k);
            int cg = cc * 64 + c;
            #pragma unroll
            for (int i = 0; i < 4; ++i) {
                ull od = dup2(sO[(rq + 32 * i) * 260 + cg]);
                #pragma unroll
                for (int k = 0; k < 8; ++k)
                    acc[i][k] = fma2(od, wv[k], acc[i][k]);
            }
        }
    }

    #pragma unroll
    for (int i = 0; i < 4; ++i) {
        int r = row0 + rq + 32 * i;
        float* orow_out = out + (size_t)((r & 1023) * 13 + (r >> 10)) * 128;
        #pragma unroll
        for (int k = 0; k < 8; ++k) {
            int f = 16 * k + fg * 2;
            float y0 = fmaxf(lo32(acc[i][k]) + sBF[f], 0.f);
            float y1 = fmaxf(hi32(acc[i][k]) + sBF[f + 1], 0.f);
            float s = y0 + y1;
            float s2 = y0 * y0 + y1 * y1;
            s  += __shfl_xor_sync(0xffffffffu, s, 1);
            s2 += __shfl_xor_sync(0xffffffffu, s2, 1);
            s  += __shfl_xor_sync(0xffffffffu, s, 2);
            s2 += __shfl_xor_sync(0xffffffffu, s2, 2);
            float mean = s * 0.125f;
            float var = s2 * 0.125f - mean * mean;
            float sc = rsqrtf(var + EPSF);
            float o0 = (y0 - mean) * sc * sGW[f] + sGB[f];
            float o1 = (y1 - mean) * sc * sGW[f + 1] + sGB[f + 1];
            *(float2*)(orow_out + f) = make_float2(o0, o1);
        }
    }
}

// ================= launch =================
extern "C" void kernel_launch(void* const* d_in, const int* in_sizes, int n_in,
                              void* d_out, int out_size) {
    (void)in_sizes; (void)n_in; (void)out_size;
    const float* x    = (const float*)d_in[0];
    const float* Wc   = (const float*)d_in[1];
    const float* bc   = (const float*)d_in[2];
    const float* ginw = (const float*)d_in[3];
    const float* ginb = (const float*)d_in[4];
    const float* Q    = (const float*)d_in[5];
    const float* Wk   = (const float*)d_in[6];
    const float* bk   = (const float*)d_in[7];
    const float* W1   = (const float*)d_in[8];
    const float* b1   = (const float*)d_in[9];
    const float* bnw  = (const float*)d_in[10];
    const float* bnb  = (const float*)d_in[11];
    const float* bnrm = (const float*)d_in[12];
    const float* bnrv = (const float*)d_in[13];
    const float* gow  = (const float*)d_in[14];
    const float* gob  = (const float*)d_in[15];
    float* out = (float*)d_out;

    cudaFuncSetAttribute(k_attention, cudaFuncAttributeMaxDynamicSharedMemorySize, SMEM_ATT_BYTES);
    cudaFuncSetAttribute(k_mlp, cudaFuncAttributeMaxDynamicSharedMemorySize, SMEM_MLP_BYTES);

    k_precompP2<<<208, 256>>>(Q, Wk, bk);                      // launch 1
    k_foldW1<<<128, 256>>>(W1, b1, bnw, bnb, bnrm, bnrv);      // launch 2
    k_nop<<<1, 32>>>();                                        // launch 3
    k_attention<<<1024, 512, SMEM_ATT_BYTES>>>(x, Wc, bc, ginw, ginb);  // launch 4 (ncu target)
    k_mlp<<<104, 256, SMEM_MLP_BYTES>>>(gow, gob, out);        // launch 5
}

// round 16
// speedup vs baseline: 1.1649x; 1.0174x over previous
#include <cuda_runtime.h>
#include <cuda_bf16.h>
#include <cstdint>

typedef unsigned long long ull;

#define EPSF 1e-5f

// ---------------- scratch ----------------
__device__ __nv_bfloat16 g_P2h[(size_t)13 * 256 * 256];  // [e][col][k] hi plane
__device__ __nv_bfloat16 g_P2l[(size_t)13 * 256 * 256];  // [e][col][k] lo plane
__device__ float g_Pb[208 * 16];                // [m][a16], 0.5 folded bias
__device__ float g_W1T[256 * 128];              // [c][f], BN-scale folded
__device__ float g_bf[128];                     // folded bias
__device__ float g_att[(size_t)13312 * 256];    // attention out, row = a*1024 + b

// ---------------- helpers ----------------
__device__ __forceinline__ ull fma2(ull a, ull b, ull c) {
    ull d;
    asm("fma.rn.f32x2 %0, %1, %2, %3;" : "=l"(d) : "l"(a), "l"(b), "l"(c));
    return d;
}
__device__ __forceinline__ ull dup2(float v) {
    ull d; unsigned r = __float_as_uint(v);
    asm("mov.b64 %0, {%1, %1};" : "=l"(d) : "r"(r));
    return d;
}
__device__ __forceinline__ float lo32(ull a) { return __uint_as_float((unsigned)(a & 0xffffffffull)); }
__device__ __forceinline__ float hi32(ull a) { return __uint_as_float((unsigned)(a >> 32)); }

__device__ __forceinline__ void cpa16(unsigned dst, const void* src) {
    asm volatile("cp.async.ca.shared.global [%0], [%1], 16;" :: "r"(dst), "l"(src));
}
__device__ __forceinline__ void cpa_commit() {
    asm volatile("cp.async.commit_group;" ::: "memory");
}
__device__ __forceinline__ void cpa_wait2() {
    asm volatile("cp.async.wait_group 2;" ::: "memory");
}
__device__ __forceinline__ unsigned s32(const void* p) {
    return (unsigned)__cvta_generic_to_shared(p);
}
__device__ __forceinline__ void ldmx4(unsigned* r, unsigned addr) {
    asm volatile("ldmatrix.sync.aligned.m8n8.x4.shared.b16 {%0,%1,%2,%3}, [%4];"
        : "=r"(r[0]), "=r"(r[1]), "=r"(r[2]), "=r"(r[3]) : "r"(addr));
}
__device__ __forceinline__ void mma16816(float* d, const unsigned* a, const unsigned* b) {
    asm volatile(
        "mma.sync.aligned.m16n8k16.row.col.f32.bf16.bf16.f32 "
        "{%0,%1,%2,%3}, {%4,%5,%6,%7}, {%8,%9}, {%0,%1,%2,%3};"
        : "+f"(d[0]), "+f"(d[1]), "+f"(d[2]), "+f"(d[3])
        : "r"(a[0]), "r"(a[1]), "r"(a[2]), "r"(a[3]), "r"(b[0]), "r"(b[1]));
}

// ================= dummy (ncu capture alignment: capture = 4th launch) =====
__global__ void k_nop() {}

// ================= fold Q into Wk, bf16-split, [e][col][k] layout ==========
__global__ void k_precompP2(const float* __restrict__ Q,
                            const float* __restrict__ Wk,
                            const float* __restrict__ bk) {
    int e = blockIdx.x >> 4;       // 0..12
    int S = blockIdx.x & 15;       // 0..15 (= hk)
    int k = threadIdx.x;           // 0..255
    int m = S * 13 + e;            // 0..207
    const float* qp = Q + m * 4;
    float q0 = qp[0], q1 = qp[1], q2 = qp[2], q3 = qp[3];
    __nv_bfloat16* dh = g_P2h + ((size_t)e * 256 + S * 16) * 256 + k;
    __nv_bfloat16* dl = g_P2l + ((size_t)e * 256 + S * 16) * 256 + k;
    #pragma unroll
    for (int a = 0; a < 13; ++a) {
        const float* wv = Wk + (size_t)(a * 64 + S * 4) * 256 + k;
        float s = 0.5f * (q0 * wv[0] + q1 * wv[256] + q2 * wv[512] + q3 * wv[768]);
        __nv_bfloat16 hi = __float2bfloat16(s);
        dh[(size_t)a * 256] = hi;
        dl[(size_t)a * 256] = __float2bfloat16(s - __bfloat162float(hi));
    }
    #pragma unroll
    for (int a = 13; a < 16; ++a) {
        dh[(size_t)a * 256] = __float2bfloat16(0.f);
        dl[(size_t)a * 256] = __float2bfloat16(0.f);
    }
    if (k < 16) {
        float v = 0.f;
        if (k < 13) {
            const float* bb = bk + k * 64 + S * 4;
            v = 0.5f * (q0 * bb[0] + q1 * bb[1] + q2 * bb[2] + q3 * bb[3]);
        }
        g_Pb[m * 16 + k] = v;
    }
}

// ================= fold BN into W1, transpose =================
__global__ void k_foldW1(const float* __restrict__ W1, const float* __restrict__ b1,
                         const float* __restrict__ bnw, const float* __restrict__ bnb,
                         const float* __restrict__ bnrm, const float* __restrict__ bnrv) {
    int f = blockIdx.x;    // 0..127
    int c = threadIdx.x;   // 0..255
    float s = bnw[f] * rsqrtf(bnrv[f] + EPSF);
    g_W1T[c * 128 + f] = W1[f * 256 + c] * s;
    if (c == 0) g_bf[f] = b1[f] * s + bnb[f] - bnrm[f] * s;
}

// ================= attention: conv+GN, bf16-split MMA logits, softmax, AV ==
// Round-15 structure but GEMM uses a DEPTH-3 cp.async pipeline:
// 16 k-rounds/chunk, 4 staging buffers, wait_group 2 (always-commit scheme).
// smem bytes:
//   AH @ 0      : 64 x 528 (A hi)                      33,792
//   AL @ 33792  : 64 x 528 (A lo)                      33,792
//   BS @ 67584  : 4 bufs x (2 planes x 128 col x 48)   49,152
//   VT @ 116736 : 256 c x 68 t fp32                    69,632
//   MS @ 186368 : 64 t x 132 col fp32                  33,792  (sx aliased)
//   PB @ 220160 : 16 warps x 64 fp32                    4,096
#define AH_OFF  0
#define AL_OFF  33792
#define BS_OFF  67584
#define VT_OFF  116736
#define MS_OFF  186368
#define PBF_OFF 220160
#define SMEM_ATT_BYTES 224256
#define BS_BUFB 12288

__global__ void __launch_bounds__(512, 1) k_attention(
    const float* __restrict__ x, const float* __restrict__ Wc,
    const float* __restrict__ bc, const float* __restrict__ ginw,
    const float* __restrict__ ginb) {
    extern __shared__ char smc[];
    __nv_bfloat16* AH = (__nv_bfloat16*)(smc + AH_OFF);
    __nv_bfloat16* AL = (__nv_bfloat16*)(smc + AL_OFF);
    float* VT  = (float*)(smc + VT_OFF);
    float* MS  = (float*)(smc + MS_OFF);
    float* sx  = MS;                      // alias: x staging, pre-GEMM only
    float* pbuf = (float*)(smc + PBF_OFF);
    const int tid = threadIdx.x;
    const int b = blockIdx.x;

    // stage x[b] (600 floats)
    for (int i = tid; i < 150; i += 512)
        ((float4*)sx)[i] = ((const float4*)(x + (size_t)b * 600))[i];
    __syncthreads();

    // ---- conv1x1 + GroupNorm(16 groups): thread pair per channel ----
    {
        const int c = tid >> 1;
        const int th = tid & 1;
        float wr[10];
        #pragma unroll
        for (int i = 0; i < 10; ++i) wr[i] = Wc[c * 10 + i];
        const float bb = bc[c];
        float vv[30];
        float s1 = 0.f, s2 = 0.f;
        #pragma unroll 6
        for (int tt = 0; tt < 30; ++tt) {
            const float* xr = sx + (th * 30 + tt) * 10;
            float h = bb;
            #pragma unroll
            for (int i = 0; i < 10; ++i) h = fmaf(wr[i], xr[i], h);
            vv[tt] = h; s1 += h; s2 = fmaf(h, h, s2);
        }
        #pragma unroll
        for (int o = 16; o; o >>= 1) {
            s1 += __shfl_xor_sync(0xffffffffu, s1, o);
            s2 += __shfl_xor_sync(0xffffffffu, s2, o);
        }
        float mean = s1 * (1.f / 960.f);
        float var = s2 * (1.f / 960.f) - mean * mean;
        float sc = ginw[c] * rsqrtf(var + EPSF);
        float sh = ginb[c] - mean * sc;
        __syncthreads();   // all conv reads of sx done before MS is reused
        #pragma unroll 6
        for (int tt = 0; tt < 30; ++tt) {
            int t = th * 30 + tt;
            float v = fmaf(vv[tt], sc, sh);
            VT[c * 68 + t] = v;
            __nv_bfloat16 hi = __float2bfloat16(v);
            AH[t * 264 + c] = hi;
            AL[t * 264 + c] = __float2bfloat16(v - __bfloat162float(hi));
        }
        if (th == 1) {
            VT[c * 68 + 60] = 0.f; VT[c * 68 + 61] = 0.f;
            VT[c * 68 + 62] = 0.f; VT[c * 68 + 63] = 0.f;
        }
    }
    // zero A pad rows t = 60..63 (both planes, incl. col pad)
    for (int i = tid; i < 4 * 264; i += 512) {
        int rr = 60 + i / 264, cc = i % 264;
        AH[rr * 264 + cc] = __float2bfloat16(0.f);
        AL[rr * 264 + cc] = __float2bfloat16(0.f);
    }
    __syncthreads();

    const int e0 = (b * 13) >> 10;
    const int e12 = (b * 13 + 12) >> 10;
    const int nchunks = (e0 == e12) ? 2 : 4;
    const int w = tid >> 5;
    const int lane = tid & 31;
    const int mt = w >> 3;          // m-tile 0..1 (rows mt*32..+32)
    const int no8 = w & 7;          // 16-col group (cols no8*16..+16)
    const int g = lane >> 2;
    const int t4 = lane & 3;

    // staging: 512 threads x 16 B per round (2 planes x 128 cols x 32B)
    const int spl = tid >> 8;              // 0 = hi, 1 = lo
    const int scol = (tid & 255) >> 1;     // local col 0..127
    const int shf_ = tid & 1;              // 16B half of the 32B payload
    const unsigned bs_t = s32(smc + BS_OFF) + (unsigned)(spl * 6144 + scol * 48 + shf_ * 16);
    const __nv_bfloat16* gsrc = spl ? g_P2l : g_P2h;

    const unsigned aA_lane = (unsigned)((lane & 15) * 528 + ((lane >> 4) & 1) * 16);
    const unsigned aAH0 = s32(AH) + (unsigned)(mt * 32 * 528) + aA_lane;
    const unsigned aAH1 = aAH0 + 16 * 528;
    const unsigned aAL0 = s32(AL) + (unsigned)(mt * 32 * 528) + aA_lane;
    const unsigned aAL1 = aAL0 + 16 * 528;
    const int bgrp = lane >> 3, blr = lane & 7;
    const unsigned bs_lane = (unsigned)((no8 * 16 + (bgrp >> 1) * 8 + blr) * 48 + (bgrp & 1) * 16);
    const unsigned bsm = s32(smc + BS_OFF);

    for (int chunk = 0; chunk < nchunks; ++chunk) {
        const int p = chunk & 1;
        const int ec = e0 + (chunk >> 1);
        const size_t qb = ((size_t)ec * 256 + p * 128 + scol) * 256 + (size_t)shf_ * 8;

        float D[2][8];
        #pragma unroll
        for (int i = 0; i < 2; ++i)
            #pragma unroll
            for (int j = 0; j < 8; ++j) D[i][j] = 0.f;

        // prologue: issue rounds 0..2 (one commit group each)
        #pragma unroll
        for (int rr = 0; rr < 3; ++rr) {
            cpa16(bs_t + (unsigned)(rr * BS_BUFB), gsrc + qb + (size_t)rr * 16);
            cpa_commit();
        }

        for (int r = 0; r < 16; ++r) {
            cpa_wait2();           // group r complete (<=2 pending)
            __syncthreads();
            if (r + 3 < 16)
                cpa16(bs_t + (unsigned)(((r + 3) & 3) * BS_BUFB),
                      gsrc + qb + (size_t)(r + 3) * 16);
            cpa_commit();          // always commit (possibly empty group)

            const unsigned bufof = (unsigned)((r & 3) * BS_BUFB);
            const unsigned kbyte = (unsigned)(r * 32);
            unsigned ah0[4], ah1[4], al0[4], al1[4];
            ldmx4(ah0, aAH0 + kbyte);
            ldmx4(ah1, aAH1 + kbyte);
            ldmx4(al0, aAL0 + kbyte);
            ldmx4(al1, aAL1 + kbyte);
            unsigned bh[4], bl[4];
            unsigned bb = bsm + bufof + bs_lane;
            ldmx4(bh, bb);
            ldmx4(bl, bb + 6144);
            #pragma unroll
            for (int nt = 0; nt < 2; ++nt) {
                const unsigned* bhf = bh + nt * 2;
                const unsigned* blf = bl + nt * 2;
                mma16816(D[0] + nt * 4, ah0, bhf);
                mma16816(D[0] + nt * 4, ah0, blf);
                mma16816(D[0] + nt * 4, al0, bhf);
                mma16816(D[1] + nt * 4, ah1, bhf);
                mma16816(D[1] + nt * 4, ah1, blf);
                mma16816(D[1] + nt * 4, al1, bhf);
            }
        }

        // D -> MS (rows = t, cols = chunk-local 0..127, stride 132)
        #pragma unroll
        for (int rh = 0; rh < 2; ++rh) {
            int row = mt * 32 + rh * 16 + g;
            #pragma unroll
            for (int nt = 0; nt < 2; ++nt) {
                int col = no8 * 16 + nt * 8 + t4 * 2;
                *(float2*)&MS[row * 132 + col] =
                    make_float2(D[rh][nt * 4 + 0], D[rh][nt * 4 + 1]);
                *(float2*)&MS[(row + 8) * 132 + col] =
                    make_float2(D[rh][nt * 4 + 2], D[rh][nt * 4 + 3]);
            }
        }
        __syncthreads();

        // ---- epilogue for this chunk: 104 rows (8 hk x 13 j) over 16 warps ----
        for (int r = w; r < 104; r += 16) {
            int hkl = r / 13;
            int j = r - hkl * 13;
            int e = (b * 13 + j) >> 10;
            if (e != ec) continue;
            int hk = (p << 3) + hkl;
            int m = hk * 13 + e;
            int colb = hkl * 16;
            int val = j * 240 + lane * 4;
            int t = val / 52;
            int a = (val - t * 52) >> 2;
            float l1 = MS[t * 132 + colb + a] + g_Pb[m * 16 + a];
            float l2 = -1e30f;
            if (lane < 28) {
                int val2 = val + 128;
                int t2 = val2 / 52;
                int a2 = (val2 - t2 * 52) >> 2;
                l2 = MS[t2 * 132 + colb + a2] + g_Pb[m * 16 + a2];
            }
            float mx = fmaxf(l1, l2);
            #pragma unroll
            for (int o = 16; o; o >>= 1) mx = fmaxf(mx, __shfl_xor_sync(0xffffffffu, mx, o));
            float x1 = __expf(l1 - mx);
            float x2 = (lane < 28) ? __expf(l2 - mx) : 0.f;
            float sum = x1 + x2;
            #pragma unroll
            for (int o = 16; o; o >>= 1) sum += __shfl_xor_sync(0xffffffffu, sum, o);
            float inv = 1.f / sum;
            pbuf[w * 64 + lane] = x1 * inv;
            if (lane < 28) pbuf[w * 64 + 32 + lane] = x2 * inv;
            __syncwarp();
            // AV: lanes 0..15 sum t 0..29, lanes 16..31 sum t 30..59
            int dh = lane & 15;
            int toff = (lane >> 4) * 30;
            const float* vcol = VT + (hk * 16 + dh) * 68 + toff;
            const float* pb = pbuf + w * 64 + toff;
            float a0 = 0.f, a1 = 0.f;
            #pragma unroll
            for (int tt = 0; tt < 15; ++tt) {
                a0 = fmaf(pb[tt], vcol[tt], a0);
                a1 = fmaf(pb[tt + 15], vcol[tt + 15], a1);
            }
            float acv = a0 + a1;
            acv += __shfl_xor_sync(0xffffffffu, acv, 16);
            if (lane < 16) {
                int bq = (b * 13 + j) & 1023;
                g_att[(size_t)((m >> 4) * 1024 + bq) * 256 + ((m & 15) << 4) + dh] = acv;
            }
            __syncwarp();
        }
        __syncthreads();   // MS reads done before next chunk overwrites
    }
}

// ================= MLP + BN + ReLU + GroupNorm + permute =================
// 104 blocks x 128 rows (round-3 proven version, 37.4 us)
#define SO_OFF   0                          // [128][260]
#define SWC_OFF  (128*260)                  // [64][132]
#define SBF_OFF  (SWC_OFF + 64*132)
#define SGW_OFF  (SBF_OFF + 128)
#define SGB_OFF  (SGW_OFF + 128)
#define SMEM_MLP_FLOATS (SGB_OFF + 128)
#define SMEM_MLP_BYTES  (SMEM_MLP_FLOATS * 4)

__global__ void __launch_bounds__(256, 1) k_mlp(const float* __restrict__ gow,
                                                const float* __restrict__ gob,
                                                float* __restrict__ out) {
    extern __shared__ float sm[];
    float* sO  = sm + SO_OFF;
    float* sW  = sm + SWC_OFF;
    float* sBF = sm + SBF_OFF;
    float* sGW = sm + SGW_OFF;
    float* sGB = sm + SGB_OFF;
    const int tid = threadIdx.x;
    const int row0 = blockIdx.x * 128;

    for (int q = tid; q < 8192; q += 256) {
        int row = q >> 6, c4 = q & 63;
        *(float4*)(sO + row * 260 + c4 * 4) =
            *(const float4*)(g_att + (size_t)(row0 + row) * 256 + c4 * 4);
    }
    if (tid < 128) { sBF[tid] = g_bf[tid]; sGW[tid] = gow[tid]; sGB[tid] = gob[tid]; }

    const int rq = tid >> 3;       // 0..31
    const int fg = tid & 7;        // f = 16k + fg*2 + {0,1}
    ull acc[4][8];
    #pragma unroll
    for (int i = 0; i < 4; ++i)
        #pragma unroll
        for (int k = 0; k < 8; ++k) acc[i][k] = 0ull;

    for (int cc = 0; cc < 4; ++cc) {
        __syncthreads();
        for (int q = tid; q < 2048; q += 256) {
            int c = q >> 5, f4 = q & 31;
            *(float4*)(sW + c * 132 + f4 * 4) =
                *(const float4*)(g_W1T + (size_t)(cc * 64 + c) * 128 + f4 * 4);
        }
        __syncthreads();
        #pragma unroll 4
        for (int c = 0; c < 64; ++c) {
            const float* wr = sW + c * 132 + fg * 2;
            ull wv[8];
            #pragma unroll
            for (int k = 0; k < 8; ++k) wv[k] = *(const ull*)(wr + 16 * k);
            int cg = cc * 64 + c;
            #pragma unroll
            for (int i = 0; i < 4; ++i) {
                ull od = dup2(sO[(rq + 32 * i) * 260 + cg]);
                #pragma unroll
                for (int k = 0; k < 8; ++k)
                    acc[i][k] = fma2(od, wv[k], acc[i][k]);
            }
        }
    }

    #pragma unroll
    for (int i = 0; i < 4; ++i) {
        int r = row0 + rq + 32 * i;
        float* orow_out = out + (size_t)((r & 1023) * 13 + (r >> 10)) * 128;
        #pragma unroll
        for (int k = 0; k < 8; ++k) {
            int f = 16 * k + fg * 2;
            float y0 = fmaxf(lo32(acc[i][k]) + sBF[f], 0.f);
            float y1 = fmaxf(hi32(acc[i][k]) + sBF[f + 1], 0.f);
            float s = y0 + y1;
            float s2 = y0 * y0 + y1 * y1;
            s  += __shfl_xor_sync(0xffffffffu, s, 1);
            s2 += __shfl_xor_sync(0xffffffffu, s2, 1);
            s  += __shfl_xor_sync(0xffffffffu, s, 2);
            s2 += __shfl_xor_sync(0xffffffffu, s2, 2);
            float mean = s * 0.125f;
            float var = s2 * 0.125f - mean * mean;
            float sc = rsqrtf(var + EPSF);
            float o0 = (y0 - mean) * sc * sGW[f] + sGB[f];
            float o1 = (y1 - mean) * sc * sGW[f + 1] + sGB[f + 1];
            *(float2*)(orow_out + f) = make_float2(o0, o1);
        }
    }
}

// ================= launch =================
extern "C" void kernel_launch(void* const* d_in, const int* in_sizes, int n_in,
                              void* d_out, int out_size) {
    (void)in_sizes; (void)n_in; (void)out_size;
    const float* x    = (const float*)d_in[0];
    const float* Wc   = (const float*)d_in[1];
    const float* bc   = (const float*)d_in[2];
    const float* ginw = (const float*)d_in[3];
    const float* ginb = (const float*)d_in[4];
    const float* Q    = (const float*)d_in[5];
    const float* Wk   = (const float*)d_in[6];
    const float* bk   = (const float*)d_in[7];
    const float* W1   = (const float*)d_in[8];
    const float* b1   = (const float*)d_in[9];
    const float* bnw  = (const float*)d_in[10];
    const float* bnb  = (const float*)d_in[11];
    const float* bnrm = (const float*)d_in[12];
    const float* bnrv = (const float*)d_in[13];
    const float* gow  = (const float*)d_in[14];
    const float* gob  = (const float*)d_in[15];
    float* out = (float*)d_out;

    cudaFuncSetAttribute(k_attention, cudaFuncAttributeMaxDynamicSharedMemorySize, SMEM_ATT_BYTES);
    cudaFuncSetAttribute(k_mlp, cudaFuncAttributeMaxDynamicSharedMemorySize, SMEM_MLP_BYTES);

    k_precompP2<<<208, 256>>>(Q, Wk, bk);                      // launch 1
    k_foldW1<<<128, 256>>>(W1, b1, bnw, bnb, bnrm, bnrv);      // launch 2
    k_nop<<<1, 32>>>();                                        // launch 3
    k_attention<<<1024, 512, SMEM_ATT_BYTES>>>(x, Wc, bc, ginw, ginb);  // launch 4 (ncu target)
    k_mlp<<<104, 256, SMEM_MLP_BYTES>>>(gow, gob, out);        // launch 5
}

// round 17
// speedup vs baseline: 1.2661x; 1.0869x over previous
#include <cuda_runtime.h>
#include <cuda_bf16.h>
#include <cstdint>

typedef unsigned long long ull;

#define EPSF 1e-5f

// ---------------- scratch ----------------
__device__ __nv_bfloat16 g_P2h[(size_t)13 * 256 * 256];  // [e][col][k] hi plane
__device__ __nv_bfloat16 g_P2l[(size_t)13 * 256 * 256];  // [e][col][k] lo plane
__device__ float g_Pb[208 * 16];                // [m][a16], 0.5 folded bias
__device__ float g_W1T[256 * 128];              // [c][f], BN-scale folded
__device__ float g_bf[128];                     // folded bias
__device__ float g_att[(size_t)13312 * 256];    // attention out, row = a*1024 + b

// ---------------- helpers ----------------
__device__ __forceinline__ ull fma2(ull a, ull b, ull c) {
    ull d;
    asm("fma.rn.f32x2 %0, %1, %2, %3;" : "=l"(d) : "l"(a), "l"(b), "l"(c));
    return d;
}
__device__ __forceinline__ ull dup2(float v) {
    ull d; unsigned r = __float_as_uint(v);
    asm("mov.b64 %0, {%1, %1};" : "=l"(d) : "r"(r));
    return d;
}
__device__ __forceinline__ float lo32(ull a) { return __uint_as_float((unsigned)(a & 0xffffffffull)); }
__device__ __forceinline__ float hi32(ull a) { return __uint_as_float((unsigned)(a >> 32)); }

__device__ __forceinline__ void cpa16(unsigned dst, const void* src) {
    asm volatile("cp.async.ca.shared.global [%0], [%1], 16;" :: "r"(dst), "l"(src));
}
__device__ __forceinline__ void cpa_commit() {
    asm volatile("cp.async.commit_group;" ::: "memory");
}
__device__ __forceinline__ void cpa_wait2() {
    asm volatile("cp.async.wait_group 2;" ::: "memory");
}
__device__ __forceinline__ unsigned s32(const void* p) {
    return (unsigned)__cvta_generic_to_shared(p);
}
__device__ __forceinline__ void ldmx4(unsigned* r, unsigned addr) {
    asm volatile("ldmatrix.sync.aligned.m8n8.x4.shared.b16 {%0,%1,%2,%3}, [%4];"
        : "=r"(r[0]), "=r"(r[1]), "=r"(r[2]), "=r"(r[3]) : "r"(addr));
}
__device__ __forceinline__ void mma16816(float* d, const unsigned* a, const unsigned* b) {
    asm volatile(
        "mma.sync.aligned.m16n8k16.row.col.f32.bf16.bf16.f32 "
        "{%0,%1,%2,%3}, {%4,%5,%6,%7}, {%8,%9}, {%0,%1,%2,%3};"
        : "+f"(d[0]), "+f"(d[1]), "+f"(d[2]), "+f"(d[3])
        : "r"(a[0]), "r"(a[1]), "r"(a[2]), "r"(a[3]), "r"(b[0]), "r"(b[1]));
}

// ================= dummy (ncu capture alignment: capture = 4th launch) =====
__global__ void k_nop() {}

// ================= fold Q into Wk, bf16-split, [e][col][k] layout ==========
__global__ void k_precompP2(const float* __restrict__ Q,
                            const float* __restrict__ Wk,
                            const float* __restrict__ bk) {
    int e = blockIdx.x >> 4;       // 0..12
    int S = blockIdx.x & 15;       // 0..15 (= hk)
    int k = threadIdx.x;           // 0..255
    int m = S * 13 + e;            // 0..207
    const float* qp = Q + m * 4;
    float q0 = qp[0], q1 = qp[1], q2 = qp[2], q3 = qp[3];
    __nv_bfloat16* dh = g_P2h + ((size_t)e * 256 + S * 16) * 256 + k;
    __nv_bfloat16* dl = g_P2l + ((size_t)e * 256 + S * 16) * 256 + k;
    #pragma unroll
    for (int a = 0; a < 13; ++a) {
        const float* wv = Wk + (size_t)(a * 64 + S * 4) * 256 + k;
        float s = 0.5f * (q0 * wv[0] + q1 * wv[256] + q2 * wv[512] + q3 * wv[768]);
        __nv_bfloat16 hi = __float2bfloat16(s);
        dh[(size_t)a * 256] = hi;
        dl[(size_t)a * 256] = __float2bfloat16(s - __bfloat162float(hi));
    }
    #pragma unroll
    for (int a = 13; a < 16; ++a) {
        dh[(size_t)a * 256] = __float2bfloat16(0.f);
        dl[(size_t)a * 256] = __float2bfloat16(0.f);
    }
    if (k < 16) {
        float v = 0.f;
        if (k < 13) {
            const float* bb = bk + k * 64 + S * 4;
            v = 0.5f * (q0 * bb[0] + q1 * bb[1] + q2 * bb[2] + q3 * bb[3]);
        }
        g_Pb[m * 16 + k] = v;
    }
}

// ================= fold BN into W1, transpose =================
__global__ void k_foldW1(const float* __restrict__ W1, const float* __restrict__ b1,
                         const float* __restrict__ bnw, const float* __restrict__ bnb,
                         const float* __restrict__ bnrm, const float* __restrict__ bnrv) {
    int f = blockIdx.x;    // 0..127
    int c = threadIdx.x;   // 0..255
    float s = bnw[f] * rsqrtf(bnrv[f] + EPSF);
    g_W1T[c * 128 + f] = W1[f * 256 + c] * s;
    if (c == 0) g_bf[f] = b1[f] * s + bnb[f] - bnrm[f] * s;
}

// ================= attention: conv+GN, bf16-split MMA logits, softmax, AV ==
// Round-16 structure; VT is now T-MAJOR ([t][c], stride 264) so AV reads are
// conflict-free (16 consecutive floats per half-warp).
// smem bytes:
//   AH @ 0      : 64 x 528 (A hi)                      33,792
//   AL @ 33792  : 64 x 528 (A lo)                      33,792
//   BS @ 67584  : 4 bufs x (2 planes x 128 col x 48)   49,152
//   VT @ 116736 : 64 t x 264 c fp32                    67,584
//   MS @ 184320 : 64 t x 132 col fp32                  33,792  (sx aliased)
//   PB @ 218112 : 16 warps x 64 fp32                    4,096
#define AH_OFF  0
#define AL_OFF  33792
#define BS_OFF  67584
#define VT_OFF  116736
#define MS_OFF  184320
#define PBF_OFF 218112
#define SMEM_ATT_BYTES 222208
#define BS_BUFB 12288

__global__ void __launch_bounds__(512, 1) k_attention(
    const float* __restrict__ x, const float* __restrict__ Wc,
    const float* __restrict__ bc, const float* __restrict__ ginw,
    const float* __restrict__ ginb) {
    extern __shared__ char smc[];
    __nv_bfloat16* AH = (__nv_bfloat16*)(smc + AH_OFF);
    __nv_bfloat16* AL = (__nv_bfloat16*)(smc + AL_OFF);
    float* VT  = (float*)(smc + VT_OFF);
    float* MS  = (float*)(smc + MS_OFF);
    float* sx  = MS;                      // alias: x staging, pre-GEMM only
    float* pbuf = (float*)(smc + PBF_OFF);
    const int tid = threadIdx.x;
    const int b = blockIdx.x;

    // stage x[b] (600 floats)
    for (int i = tid; i < 150; i += 512)
        ((float4*)sx)[i] = ((const float4*)(x + (size_t)b * 600))[i];
    __syncthreads();

    // ---- conv1x1 + GroupNorm(16 groups): thread pair per channel ----
    {
        const int c = tid >> 1;
        const int th = tid & 1;
        float wr[10];
        #pragma unroll
        for (int i = 0; i < 10; ++i) wr[i] = Wc[c * 10 + i];
        const float bb = bc[c];
        float vv[30];
        float s1 = 0.f, s2 = 0.f;
        #pragma unroll 6
        for (int tt = 0; tt < 30; ++tt) {
            const float* xr = sx + (th * 30 + tt) * 10;
            float h = bb;
            #pragma unroll
            for (int i = 0; i < 10; ++i) h = fmaf(wr[i], xr[i], h);
            vv[tt] = h; s1 += h; s2 = fmaf(h, h, s2);
        }
        #pragma unroll
        for (int o = 16; o; o >>= 1) {
            s1 += __shfl_xor_sync(0xffffffffu, s1, o);
            s2 += __shfl_xor_sync(0xffffffffu, s2, o);
        }
        float mean = s1 * (1.f / 960.f);
        float var = s2 * (1.f / 960.f) - mean * mean;
        float sc = ginw[c] * rsqrtf(var + EPSF);
        float sh = ginb[c] - mean * sc;
        __syncthreads();   // all conv reads of sx done before MS is reused
        #pragma unroll 6
        for (int tt = 0; tt < 30; ++tt) {
            int t = th * 30 + tt;
            float v = fmaf(vv[tt], sc, sh);
            VT[t * 264 + c] = v;           // t-major: conflict-free AV reads
            __nv_bfloat16 hi = __float2bfloat16(v);
            AH[t * 264 + c] = hi;
            AL[t * 264 + c] = __float2bfloat16(v - __bfloat162float(hi));
        }
    }
    // zero A pad rows t = 60..63 (both planes, incl. col pad)
    for (int i = tid; i < 4 * 264; i += 512) {
        int rr = 60 + i / 264, cc = i % 264;
        AH[rr * 264 + cc] = __float2bfloat16(0.f);
        AL[rr * 264 + cc] = __float2bfloat16(0.f);
    }
    __syncthreads();

    const int e0 = (b * 13) >> 10;
    const int e12 = (b * 13 + 12) >> 10;
    const int nchunks = (e0 == e12) ? 2 : 4;
    const int w = tid >> 5;
    const int lane = tid & 31;
    const int mt = w >> 3;          // m-tile 0..1 (rows mt*32..+32)
    const int no8 = w & 7;          // 16-col group (cols no8*16..+16)
    const int g = lane >> 2;
    const int t4 = lane & 3;

    // staging: 512 threads x 16 B per round (2 planes x 128 cols x 32B)
    const int spl = tid >> 8;              // 0 = hi, 1 = lo
    const int scol = (tid & 255) >> 1;     // local col 0..127
    const int shf_ = tid & 1;              // 16B half of the 32B payload
    const unsigned bs_t = s32(smc + BS_OFF) + (unsigned)(spl * 6144 + scol * 48 + shf_ * 16);
    const __nv_bfloat16* gsrc = spl ? g_P2l : g_P2h;

    const unsigned aA_lane = (unsigned)((lane & 15) * 528 + ((lane >> 4) & 1) * 16);
    const unsigned aAH0 = s32(AH) + (unsigned)(mt * 32 * 528) + aA_lane;
    const unsigned aAH1 = aAH0 + 16 * 528;
    const unsigned aAL0 = s32(AL) + (unsigned)(mt * 32 * 528) + aA_lane;
    const unsigned aAL1 = aAL0 + 16 * 528;
    const int bgrp = lane >> 3, blr = lane & 7;
    const unsigned bs_lane = (unsigned)((no8 * 16 + (bgrp >> 1) * 8 + blr) * 48 + (bgrp & 1) * 16);
    const unsigned bsm = s32(smc + BS_OFF);

    for (int chunk = 0; chunk < nchunks; ++chunk) {
        const int p = chunk & 1;
        const int ec = e0 + (chunk >> 1);
        const size_t qb = ((size_t)ec * 256 + p * 128 + scol) * 256 + (size_t)shf_ * 8;

        float D[2][8];
        #pragma unroll
        for (int i = 0; i < 2; ++i)
            #pragma unroll
            for (int j = 0; j < 8; ++j) D[i][j] = 0.f;

        // prologue: issue rounds 0..2 (one commit group each)
        #pragma unroll
        for (int rr = 0; rr < 3; ++rr) {
            cpa16(bs_t + (unsigned)(rr * BS_BUFB), gsrc + qb + (size_t)rr * 16);
            cpa_commit();
        }

        for (int r = 0; r < 16; ++r) {
            cpa_wait2();           // group r complete (<=2 pending)
            __syncthreads();
            if (r + 3 < 16)
                cpa16(bs_t + (unsigned)(((r + 3) & 3) * BS_BUFB),
                      gsrc + qb + (size_t)(r + 3) * 16);
            cpa_commit();          // always commit (possibly empty group)

            const unsigned bufof = (unsigned)((r & 3) * BS_BUFB);
            const unsigned kbyte = (unsigned)(r * 32);
            unsigned ah0[4], ah1[4], al0[4], al1[4];
            ldmx4(ah0, aAH0 + kbyte);
            ldmx4(ah1, aAH1 + kbyte);
            ldmx4(al0, aAL0 + kbyte);
            ldmx4(al1, aAL1 + kbyte);
            unsigned bh[4], bl[4];
            unsigned bb = bsm + bufof + bs_lane;
            ldmx4(bh, bb);
            ldmx4(bl, bb + 6144);
            #pragma unroll
            for (int nt = 0; nt < 2; ++nt) {
                const unsigned* bhf = bh + nt * 2;
                const unsigned* blf = bl + nt * 2;
                mma16816(D[0] + nt * 4, ah0, bhf);
                mma16816(D[0] + nt * 4, ah0, blf);
                mma16816(D[0] + nt * 4, al0, bhf);
                mma16816(D[1] + nt * 4, ah1, bhf);
                mma16816(D[1] + nt * 4, ah1, blf);
                mma16816(D[1] + nt * 4, al1, bhf);
            }
        }

        // D -> MS (rows = t, cols = chunk-local 0..127, stride 132)
        #pragma unroll
        for (int rh = 0; rh < 2; ++rh) {
            int row = mt * 32 + rh * 16 + g;
            #pragma unroll
            for (int nt = 0; nt < 2; ++nt) {
                int col = no8 * 16 + nt * 8 + t4 * 2;
                *(float2*)&MS[row * 132 + col] =
                    make_float2(D[rh][nt * 4 + 0], D[rh][nt * 4 + 1]);
                *(float2*)&MS[(row + 8) * 132 + col] =
                    make_float2(D[rh][nt * 4 + 2], D[rh][nt * 4 + 3]);
            }
        }
        __syncthreads();

        // ---- epilogue for this chunk: 104 rows (8 hk x 13 j) over 16 warps ----
        for (int r = w; r < 104; r += 16) {
            int hkl = r / 13;
            int j = r - hkl * 13;
            int e = (b * 13 + j) >> 10;
            if (e != ec) continue;
            int hk = (p << 3) + hkl;
            int m = hk * 13 + e;
            int colb = hkl * 16;
            int val = j * 240 + lane * 4;
            int t = val / 52;
            int a = (val - t * 52) >> 2;
            float l1 = MS[t * 132 + colb + a] + g_Pb[m * 16 + a];
            float l2 = -1e30f;
            if (lane < 28) {
                int val2 = val + 128;
                int t2 = val2 / 52;
                int a2 = (val2 - t2 * 52) >> 2;
                l2 = MS[t2 * 132 + colb + a2] + g_Pb[m * 16 + a2];
            }
            float mx = fmaxf(l1, l2);
            #pragma unroll
            for (int o = 16; o; o >>= 1) mx = fmaxf(mx, __shfl_xor_sync(0xffffffffu, mx, o));
            float x1 = __expf(l1 - mx);
            float x2 = (lane < 28) ? __expf(l2 - mx) : 0.f;
            float sum = x1 + x2;
            #pragma unroll
            for (int o = 16; o; o >>= 1) sum += __shfl_xor_sync(0xffffffffu, sum, o);
            float inv = 1.f / sum;
            pbuf[w * 64 + lane] = x1 * inv;
            if (lane < 28) pbuf[w * 64 + 32 + lane] = x2 * inv;
            __syncwarp();
            // AV: lanes 0..15 sum t 0..29, lanes 16..31 sum t 30..59 (VT t-major)
            int dh = lane & 15;
            int toff = (lane >> 4) * 30;
            int c = hk * 16 + dh;
            const float* vcol = VT + toff * 264 + c;
            const float* pb = pbuf + w * 64 + toff;
            float a0 = 0.f, a1 = 0.f;
            #pragma unroll
            for (int tt = 0; tt < 15; ++tt) {
                a0 = fmaf(pb[tt], vcol[tt * 264], a0);
                a1 = fmaf(pb[tt + 15], vcol[(tt + 15) * 264], a1);
            }
            float acv = a0 + a1;
            acv += __shfl_xor_sync(0xffffffffu, acv, 16);
            if (lane < 16) {
                int bq = (b * 13 + j) & 1023;
                g_att[(size_t)((m >> 4) * 1024 + bq) * 256 + ((m & 15) << 4) + dh] = acv;
            }
            __syncwarp();
        }
        __syncthreads();   // MS reads done before next chunk overwrites
    }
}

// ================= MLP + BN + ReLU + GroupNorm + permute =================
// 139 blocks x 96 rows (one full wave on 148 SMs), guarded tail.
#define MROWS    96
#define MBLOCKS  139
#define SO_OFF   0                          // [96][260]
#define SWC_OFF  (MROWS*260)                // [64][132]
#define SBF_OFF  (SWC_OFF + 64*132)
#define SGW_OFF  (SBF_OFF + 128)
#define SGB_OFF  (SGW_OFF + 128)
#define SMEM_MLP_FLOATS (SGB_OFF + 128)
#define SMEM_MLP_BYTES  (SMEM_MLP_FLOATS * 4)

__global__ void __launch_bounds__(256, 1) k_mlp(const float* __restrict__ gow,
                                                const float* __restrict__ gob,
                                                float* __restrict__ out) {
    extern __shared__ float sm[];
    float* sO  = sm + SO_OFF;
    float* sW  = sm + SWC_OFF;
    float* sBF = sm + SBF_OFF;
    float* sGW = sm + SGW_OFF;
    float* sGB = sm + SGB_OFF;
    const int tid = threadIdx.x;
    const int row0 = blockIdx.x * MROWS;

    for (int q = tid; q < MROWS * 64; q += 256) {
        int row = q >> 6, c4 = q & 63;
        float4 v = make_float4(0.f, 0.f, 0.f, 0.f);
        if (row0 + row < 13312)
            v = *(const float4*)(g_att + (size_t)(row0 + row) * 256 + c4 * 4);
        *(float4*)(sO + row * 260 + c4 * 4) = v;
    }
    if (tid < 128) { sBF[tid] = g_bf[tid]; sGW[tid] = gow[tid]; sGB[tid] = gob[tid]; }

    const int rq = tid >> 3;       // 0..31
    const int fg = tid & 7;        // f = 16k + fg*2 + {0,1}
    ull acc[3][8];
    #pragma unroll
    for (int i = 0; i < 3; ++i)
        #pragma unroll
        for (int k = 0; k < 8; ++k) acc[i][k] = 0ull;

    for (int cc = 0; cc < 4; ++cc) {
        __syncthreads();
        for (int q = tid; q < 2048; q += 256) {
            int c = q >> 5, f4 = q & 31;
            *(float4*)(sW + c * 132 + f4 * 4) =
                *(const float4*)(g_W1T + (size_t)(cc * 64 + c) * 128 + f4 * 4);
        }
        __syncthreads();
        #pragma unroll 4
        for (int c = 0; c < 64; ++c) {
            const float* wr = sW + c * 132 + fg * 2;
            ull wv[8];
            #pragma unroll
            for (int k = 0; k < 8; ++k) wv[k] = *(const ull*)(wr + 16 * k);
            int cg = cc * 64 + c;
            #pragma unroll
            for (int i = 0; i < 3; ++i) {
                ull od = dup2(sO[(rq + 32 * i) * 260 + cg]);
                #pragma unroll
                for (int k = 0; k < 8; ++k)
                    acc[i][k] = fma2(od, wv[k], acc[i][k]);
            }
        }
    }

    #pragma unroll
    for (int i = 0; i < 3; ++i) {
        int r = row0 + rq + 32 * i;
        if (r >= 13312) continue;
        float* orow_out = out + (size_t)((r & 1023) * 13 + (r >> 10)) * 128;
        #pragma unroll
        for (int k = 0; k < 8; ++k) {
            int f = 16 * k + fg * 2;
            float y0 = fmaxf(lo32(acc[i][k]) + sBF[f], 0.f);
            float y1 = fmaxf(hi32(acc[i][k]) + sBF[f + 1], 0.f);
            float s = y0 + y1;
            float s2 = y0 * y0 + y1 * y1;
            s  += __shfl_xor_sync(0xffffffffu, s, 1);
            s2 += __shfl_xor_sync(0xffffffffu, s2, 1);
            s  += __shfl_xor_sync(0xffffffffu, s, 2);
            s2 += __shfl_xor_sync(0xffffffffu, s2, 2);
            float mean = s * 0.125f;
            float var = s2 * 0.125f - mean * mean;
            float sc = rsqrtf(var + EPSF);
            float o0 = (y0 - mean) * sc * sGW[f] + sGB[f];
            float o1 = (y1 - mean) * sc * sGW[f + 1] + sGB[f + 1];
            *(float2*)(orow_out + f) = make_float2(o0, o1);
        }
    }
}

// ================= launch =================
extern "C" void kernel_launch(void* const* d_in, const int* in_sizes, int n_in,
                              void* d_out, int out_size) {
    (void)in_sizes; (void)n_in; (void)out_size;
    const float* x    = (const float*)d_in[0];
    const float* Wc   = (const float*)d_in[1];
    const float* bc   = (const float*)d_in[2];
    const float* ginw = (const float*)d_in[3];
    const float* ginb = (const float*)d_in[4];
    const float* Q    = (const float*)d_in[5];
    const float* Wk   = (const float*)d_in[6];
    const float* bk   = (const float*)d_in[7];
    const float* W1   = (const float*)d_in[8];
    const float* b1   = (const float*)d_in[9];
    const float* bnw  = (const float*)d_in[10];
    const float* bnb  = (const float*)d_in[11];
    const float* bnrm = (const float*)d_in[12];
    const float* bnrv = (const float*)d_in[13];
    const float* gow  = (const float*)d_in[14];
    const float* gob  = (const float*)d_in[15];
    float* out = (float*)d_out;

    cudaFuncSetAttribute(k_attention, cudaFuncAttributeMaxDynamicSharedMemorySize, SMEM_ATT_BYTES);
    cudaFuncSetAttribute(k_mlp, cudaFuncAttributeMaxDynamicSharedMemorySize, SMEM_MLP_BYTES);

    k_precompP2<<<208, 256>>>(Q, Wk, bk);                      // launch 1
    k_foldW1<<<128, 256>>>(W1, b1, bnw, bnb, bnrm, bnrv);      // launch 2
    k_nop<<<1, 32>>>();                                        // launch 3
    k_attention<<<1024, 512, SMEM_ATT_BYTES>>>(x, Wc, bc, ginw, ginb);  // launch 4 (ncu target)
    k_mlp<<<MBLOCKS, 256, SMEM_MLP_BYTES>>>(gow, gob, out);    // launch 5
}